// round 11
// baseline (speedup 1.0000x reference)
#include <cuda_runtime.h>
#include <cuda_fp16.h>
#include <math.h>
#include <stdint.h>

#define LOG2E_F 1.4426950408889634f

// ---------------- scratch (static device globals; no allocs) ----------------
__device__ float  g_K[32 * 64 * 1024];        // M' -> K~ (in place)       8 MB
__device__ float  g_r[32 * 65];               // Sinkhorn row scalings
__device__ float  g_c[32 * 1024];             // Sinkhorn col scalings
__device__ float  g_vpart[32 * 8 * 64 * 128]; // split-K partials of p@f
__device__ float  g_pspart[32 * 8 * 64];      // split-K partials of rowsum(p)
__device__ float  g_t[32 * 256];              // t = x0 @ Wt + bt
__device__ __half g_Bhi[192 * 768];           // (W^T * 256) hi, [n][k]
__device__ __half g_Blo[192 * 768];           // (W^T * 256) lo
__device__ __half g_fh[32 * 1024 * 128];      // f hi (half)              8 MB
__device__ __half g_fl[32 * 1024 * 128];      // f lo (half)              8 MB

// ------------------------------- helpers -------------------------------------
__device__ __forceinline__ float warpSum(float v) {
    #pragma unroll
    for (int o = 16; o > 0; o >>= 1) v += __shfl_xor_sync(0xffffffffu, v, o);
    return v;
}
__device__ __forceinline__ float warpMax(float v) {
    #pragma unroll
    for (int o = 16; o > 0; o >>= 1) v = fmaxf(v, __shfl_xor_sync(0xffffffffu, v, o));
    return v;
}
// exp2 on the FMA pipe (x <= 0 here). deg-5 Taylor, rel err ~2e-6.
__device__ __forceinline__ float exp2_fma(float x) {
    x = fmaxf(x, -125.0f);
    int   ni = __float2int_rn(x);
    float f  = x - (float)ni;
    float p  = 1.3333558e-3f;
    p = fmaf(p, f, 9.6181290e-3f);
    p = fmaf(p, f, 5.5504109e-2f);
    p = fmaf(p, f, 2.4022651e-1f);
    p = fmaf(p, f, 6.9314718e-1f);
    p = fmaf(p, f, 1.0f);
    return p * __int_as_float((ni + 127) << 23);
}
__device__ __forceinline__ void mma16816(float* d, uint32_t a0, uint32_t a1,
                                         uint32_t a2, uint32_t a3,
                                         uint32_t b0, uint32_t b1) {
    asm volatile(
        "mma.sync.aligned.m16n8k16.row.col.f32.f16.f16.f32 "
        "{%0,%1,%2,%3}, {%4,%5,%6,%7}, {%8,%9}, {%0,%1,%2,%3};"
        : "+f"(d[0]), "+f"(d[1]), "+f"(d[2]), "+f"(d[3])
        : "r"(a0), "r"(a1), "r"(a2), "r"(a3), "r"(b0), "r"(b1));
}
__device__ __forceinline__ void ldsm4(uint32_t& r0, uint32_t& r1,
                                      uint32_t& r2, uint32_t& r3, uint32_t a) {
    asm volatile("ldmatrix.sync.aligned.m8n8.x4.shared.b16 {%0,%1,%2,%3}, [%4];"
                 : "=r"(r0), "=r"(r1), "=r"(r2), "=r"(r3) : "r"(a));
}
__device__ __forceinline__ void ldsm4t(uint32_t& r0, uint32_t& r1,
                                       uint32_t& r2, uint32_t& r3, uint32_t a) {
    asm volatile("ldmatrix.sync.aligned.m8n8.x4.trans.shared.b16 {%0,%1,%2,%3}, [%4];"
                 : "=r"(r0), "=r"(r1), "=r"(r2), "=r"(r3) : "r"(a));
}
__device__ __forceinline__ uint32_t pack_h2(__half a, __half b) {
    __half2 h = __halves2half2(a, b);
    return *(uint32_t*)&h;
}
__device__ __forceinline__ uint32_t smem_u32(const void* p) {
    uint32_t a;
    asm("{ .reg .u64 t; cvta.to.shared.u64 t, %1; cvt.u32.u64 %0, t; }" : "=r"(a) : "l"(p));
    return a;
}
__device__ __forceinline__ void cpasync16(uint32_t dst, const void* src) {
    asm volatile("cp.async.cg.shared.global [%0], [%1], 16;" :: "r"(dst), "l"(src));
}
#define CP_COMMIT() asm volatile("cp.async.commit_group;" ::: "memory")
#define CP_WAIT0()  asm volatile("cp.async.wait_group 0;" ::: "memory")

// ---- prep: fused W-split (blocks 0..575) + t-GEMM (blocks 576..607) ---------
__global__ __launch_bounds__(256) void prep(
    const float* __restrict__ Wf, const float* __restrict__ Ws,
    const float* __restrict__ x, const float* __restrict__ Wt,
    const float* __restrict__ bt)
{
    const int blk = blockIdx.x;
    __shared__ float xs[768];
    if (blk < 384) {
        int i = blk * 256 + threadIdx.x;            // 128*768
        int n = i / 768, k = i - n * 768;
        float v = Wf[(size_t)k * 128 + n] * 256.0f;
        __half hi = __float2half_rn(v);
        g_Bhi[i] = hi;
        g_Blo[i] = __float2half_rn(v - __half2float(hi));
    } else if (blk < 576) {
        int i = (blk - 384) * 256 + threadIdx.x;    // 64*768
        int n = i / 768, k = i - n * 768;
        float v = Ws[(size_t)k * 64 + n] * 256.0f;
        __half hi = __float2half_rn(v);
        g_Bhi[128 * 768 + i] = hi;
        g_Blo[128 * 768 + i] = __float2half_rn(v - __half2float(hi));
    } else {
        const int b = blk - 576;
        const int c = threadIdx.x;
        for (int i = c; i < 768; i += 256) xs[i] = x[(size_t)b * 1025 * 768 + i];
        __syncthreads();
        float acc = bt[c];
        #pragma unroll 8
        for (int d = 0; d < 768; d++) acc = fmaf(xs[d], Wt[(size_t)d * 256 + c], acc);
        g_t[b * 256 + c] = acc;
    }
}

// ---------------------------------------------------------------------------
// gemmA via mma.sync + ldmatrix, double-buffered A and B smem. (unchanged)
// ---------------------------------------------------------------------------
#define A_MAT  18432
#define SMA_HI(buf) ((buf) * (2 * A_MAT))
#define SMA_LO_OFF A_MAT
#define B_HI_SZ 27648
#define B_LOS_SZ 9216
#define B_BUF (B_HI_SZ + B_LOS_SZ)
#define SMB_HI(buf) (4 * A_MAT + (buf) * B_BUF)
#define SMB_LOS_OFF B_HI_SZ
#define SM_TOTAL (4 * A_MAT + 2 * B_BUF)      // 147456 B

__global__ __launch_bounds__(512) void gemmA_mma(
    const float* __restrict__ x, const float* __restrict__ bf,
    const float* __restrict__ bs, const float* __restrict__ sharp)
{
    extern __shared__ char sm[];
    const uint32_t smu = smem_u32(sm);
    const int tid = threadIdx.x, wid = tid >> 5, lane = tid & 31;
    const int b = blockIdx.y, nt = blockIdx.x;
    const int wr = wid & 3, wc = wid >> 2;
    const int g = lane >> 2, tig = lane & 3;

    const int rl = lane & 15, kh = lane >> 4;
    const uint32_t aOff   = (uint32_t)((wr * 32 + rl) * 144 + kh * 16);
    const uint32_t bfOff  = (uint32_t)((wc * 32 + rl) * 144 + kh * 16);
    const uint32_t bshOff = (uint32_t)((128 + wc * 16 + rl) * 144 + kh * 16);
    const uint32_t bslOff = (uint32_t)(SMB_LOS_OFF + (wc * 16 + rl) * 144 + kh * 16);

    const float* A = x + (size_t)b * 1025 * 768 + 768 + (size_t)nt * 128 * 768;
    const int am = tid >> 2, akb = (tid & 3) * 16;
    const float* aptr = A + (size_t)am * 768 + akb;
    const uint32_t cvtOff = (uint32_t)(am * 144 + akb * 2);

    float acc[2][6][4];
    float accS2[2][2][4];
    #pragma unroll
    for (int mf = 0; mf < 2; mf++) {
        #pragma unroll
        for (int nf = 0; nf < 6; nf++)
            #pragma unroll
            for (int q = 0; q < 4; q++) acc[mf][nf][q] = 0.0f;
        #pragma unroll
        for (int nf = 0; nf < 2; nf++)
            #pragma unroll
            for (int q = 0; q < 4; q++) accS2[mf][nf][q] = 0.0f;
    }

    float4 aPre[4];
    uint4 h0, h1, l0, l1;

    #define CONVERT_A(WBUF)                                                     \
    do {                                                                        \
        char* dhi = sm + SMA_HI(WBUF) + cvtOff;                                 \
        _Pragma("unroll")                                                       \
        for (int i = 0; i < 4; i++) {                                           \
            float4 v = aPre[i];                                                 \
            __half hx = __float2half_rn(v.x), hy = __float2half_rn(v.y);        \
            __half hz = __float2half_rn(v.z), hw = __float2half_rn(v.w);        \
            __half lx = __float2half_rn(v.x - __half2float(hx));                \
            __half ly = __float2half_rn(v.y - __half2float(hy));                \
            __half lz = __float2half_rn(v.z - __half2float(hz));                \
            __half lw = __float2half_rn(v.w - __half2float(hw));                \
            uint32_t hqa = pack_h2(hx, hy), hqb = pack_h2(hz, hw);              \
            uint32_t lqa = pack_h2(lx, ly), lqb = pack_h2(lz, lw);              \
            if (i == 0) { h0.x = hqa; h0.y = hqb; l0.x = lqa; l0.y = lqb; }     \
            else if (i == 1) { h0.z = hqa; h0.w = hqb; l0.z = lqa; l0.w = lqb; }\
            else if (i == 2) { h1.x = hqa; h1.y = hqb; l1.x = lqa; l1.y = lqb; }\
            else { h1.z = hqa; h1.w = hqb; l1.z = lqa; l1.w = lqb; }            \
        }                                                                       \
        *(uint4*)(dhi) = h0;  *(uint4*)(dhi + 16) = h1;                         \
        *(uint4*)(dhi + SMA_LO_OFF) = l0; *(uint4*)(dhi + SMA_LO_OFF + 16) = l1;\
    } while (0)

    #define FETCH_B(CH, WBUF)                                                   \
    do {                                                                        \
        const int kk0 = (CH) * 64;                                              \
        _Pragma("unroll")                                                       \
        for (int j = 0; j < 3; j++) {                                           \
            int e = tid + j * 512;                                              \
            int n = e >> 3, u = e & 7;                                          \
            cpasync16(smu + SMB_HI(WBUF) + (uint32_t)(n * 144 + u * 16),        \
                      g_Bhi + (size_t)n * 768 + kk0 + u * 8);                   \
        }                                                                       \
        {                                                                       \
            int n = tid >> 3, u = tid & 7;                                      \
            if (n < 64)                                                         \
                cpasync16(smu + SMB_HI(WBUF) + SMB_LOS_OFF +                    \
                          (uint32_t)(n * 144 + u * 16),                         \
                          g_Blo + (size_t)(128 + n) * 768 + kk0 + u * 8);       \
        }                                                                       \
        CP_COMMIT();                                                            \
    } while (0)

    // ---- prologue ----
    #pragma unroll
    for (int i = 0; i < 4; i++) aPre[i] = *(const float4*)(aptr + i * 4);
    FETCH_B(0, 0);
    CONVERT_A(0);
    #pragma unroll
    for (int i = 0; i < 4; i++) aPre[i] = *(const float4*)(aptr + 64 + i * 4);
    CP_WAIT0();
    __syncthreads();

    #pragma unroll 1
    for (int ch = 0; ch < 12; ch++) {
        const int buf = ch & 1;
        if (ch < 11) {
            FETCH_B(ch + 1, buf ^ 1);
            CONVERT_A(buf ^ 1);
            if (ch < 10) {
                const int k2 = (ch + 2) * 64;
                #pragma unroll
                for (int i = 0; i < 4; i++) aPre[i] = *(const float4*)(aptr + k2 + i * 4);
            }
        }

        const uint32_t aHiB = smu + SMA_HI(buf) + aOff;
        const uint32_t aLoB = aHiB + SMA_LO_OFF;
        const uint32_t bHfB = smu + SMB_HI(buf) + bfOff;
        const uint32_t bHsB = smu + SMB_HI(buf) + bshOff;
        const uint32_t bLsB = smu + SMB_HI(buf) + bslOff;
        #pragma unroll
        for (int ks = 0; ks < 4; ks++) {
            const uint32_t ko = ks * 32;
            uint32_t ah[2][4], al[2][4];
            uint32_t bsh0, bsh1, bsh2, bsh3, bsl0, bsl1, bsl2, bsl3;
            uint32_t bfa[4], bfb[4];
            ldsm4(ah[0][0], ah[0][1], ah[0][2], ah[0][3], aHiB + ko);
            ldsm4(ah[1][0], ah[1][1], ah[1][2], ah[1][3], aHiB + 16 * 144 + ko);
            ldsm4(bsh0, bsh1, bsh2, bsh3, bHsB + ko);
            ldsm4(al[0][0], al[0][1], al[0][2], al[0][3], aLoB + ko);
            ldsm4(al[1][0], al[1][1], al[1][2], al[1][3], aLoB + 16 * 144 + ko);
            ldsm4(bsl0, bsl1, bsl2, bsl3, bLsB + ko);
            ldsm4(bfa[0], bfa[1], bfa[2], bfa[3], bHfB + ko);
            ldsm4(bfb[0], bfb[1], bfb[2], bfb[3], bHfB + 16 * 144 + ko);

            mma16816(acc[0][4], ah[0][0], ah[0][1], ah[0][2], ah[0][3], bsh0, bsh2);
            mma16816(acc[0][5], ah[0][0], ah[0][1], ah[0][2], ah[0][3], bsh1, bsh3);
            mma16816(acc[1][4], ah[1][0], ah[1][1], ah[1][2], ah[1][3], bsh0, bsh2);
            mma16816(acc[1][5], ah[1][0], ah[1][1], ah[1][2], ah[1][3], bsh1, bsh3);
            mma16816(acc[0][0], ah[0][0], ah[0][1], ah[0][2], ah[0][3], bfa[0], bfa[2]);
            mma16816(acc[0][1], ah[0][0], ah[0][1], ah[0][2], ah[0][3], bfa[1], bfa[3]);
            mma16816(acc[1][0], ah[1][0], ah[1][1], ah[1][2], ah[1][3], bfa[0], bfa[2]);
            mma16816(acc[1][1], ah[1][0], ah[1][1], ah[1][2], ah[1][3], bfa[1], bfa[3]);
            mma16816(accS2[0][0], ah[0][0], ah[0][1], ah[0][2], ah[0][3], bsl0, bsl2);
            mma16816(accS2[0][1], ah[0][0], ah[0][1], ah[0][2], ah[0][3], bsl1, bsl3);
            mma16816(accS2[1][0], ah[1][0], ah[1][1], ah[1][2], ah[1][3], bsl0, bsl2);
            mma16816(accS2[1][1], ah[1][0], ah[1][1], ah[1][2], ah[1][3], bsl1, bsl3);
            mma16816(acc[0][2], ah[0][0], ah[0][1], ah[0][2], ah[0][3], bfb[0], bfb[2]);
            mma16816(acc[0][3], ah[0][0], ah[0][1], ah[0][2], ah[0][3], bfb[1], bfb[3]);
            mma16816(acc[1][2], ah[1][0], ah[1][1], ah[1][2], ah[1][3], bfb[0], bfb[2]);
            mma16816(acc[1][3], ah[1][0], ah[1][1], ah[1][2], ah[1][3], bfb[1], bfb[3]);
            mma16816(acc[0][4], al[0][0], al[0][1], al[0][2], al[0][3], bsh0, bsh2);
            mma16816(acc[0][5], al[0][0], al[0][1], al[0][2], al[0][3], bsh1, bsh3);
            mma16816(acc[1][4], al[1][0], al[1][1], al[1][2], al[1][3], bsh0, bsh2);
            mma16816(acc[1][5], al[1][0], al[1][1], al[1][2], al[1][3], bsh1, bsh3);
        }
        if (ch < 11) CP_WAIT0();
        __syncthreads();
    }

    // ---------------------------- epilogue ----------------------------------
    const float inv256 = 1.0f / 256.0f;
    const float scl = sharp[0] * 10.0f * LOG2E_F;
    #pragma unroll
    for (int mf = 0; mf < 2; mf++) {
        #pragma unroll
        for (int nf = 0; nf < 4; nf++) {
            int c = wc * 32 + nf * 8 + tig * 2;
            int r0 = nt * 128 + wr * 32 + mf * 16 + g;
            int r1 = r0 + 8;
            float b0 = __ldg(bf + c), b1 = __ldg(bf + c + 1);
            float f00 = fmaf(acc[mf][nf][0], inv256, b0);
            float f01 = fmaf(acc[mf][nf][1], inv256, b1);
            float f10 = fmaf(acc[mf][nf][2], inv256, b0);
            float f11 = fmaf(acc[mf][nf][3], inv256, b1);
            __half h00 = __float2half_rn(f00), h01 = __float2half_rn(f01);
            __half h10 = __float2half_rn(f10), h11 = __float2half_rn(f11);
            size_t i0 = ((size_t)(b * 1024 + r0)) * 128 + c;
            size_t i1 = ((size_t)(b * 1024 + r1)) * 128 + c;
            *(uint32_t*)(g_fh + i0) = pack_h2(h00, h01);
            *(uint32_t*)(g_fh + i1) = pack_h2(h10, h11);
            *(uint32_t*)(g_fl + i0) = pack_h2(__float2half_rn(f00 - __half2float(h00)),
                                              __float2half_rn(f01 - __half2float(h01)));
            *(uint32_t*)(g_fl + i1) = pack_h2(__float2half_rn(f10 - __half2float(h10)),
                                              __float2half_rn(f11 - __half2float(h11)));
        }
        #pragma unroll
        for (int nf = 4; nf < 6; nf++) {
            int k = wc * 16 + (nf - 4) * 8 + tig * 2;
            int r0 = nt * 128 + wr * 32 + mf * 16 + g;
            int r1 = r0 + 8;
            float b0 = __ldg(bs + k), b1 = __ldg(bs + k + 1);
            float* K0 = g_K + ((size_t)(b * 64 + k)) * 1024;
            float* K1 = g_K + ((size_t)(b * 64 + k + 1)) * 1024;
            float d0 = acc[mf][nf][0] + accS2[mf][nf - 4][0];
            float d1 = acc[mf][nf][1] + accS2[mf][nf - 4][1];
            float d2 = acc[mf][nf][2] + accS2[mf][nf - 4][2];
            float d3 = acc[mf][nf][3] + accS2[mf][nf - 4][3];
            K0[r0] = fmaf(d0, inv256, b0) * scl;
            K1[r0] = fmaf(d1, inv256, b1) * scl;
            K0[r1] = fmaf(d2, inv256, b0) * scl;
            K1[r1] = fmaf(d3, inv256, b1) * scl;
        }
    }
}

// ------ sinkhorn: fused exp phase + 5 c-updates + 4 r-updates, float4 --------
__global__ __launch_bounds__(1024) void sinkhorn()
{
    const int b = blockIdx.x;
    const int t = threadIdx.x, w = t >> 5, l = t & 31;
    __shared__ float4 cs4[256];
    __shared__ float4 part[1024];
    __shared__ float rs[72];
    __shared__ float red[32];
    float* Kb = g_K + ((size_t)b << 16);

    // ---- phase 1: rowmax + exp2 + rowsum (warp w -> rows w, w+32), float4 ----
    #pragma unroll
    for (int rr = 0; rr < 2; rr++) {
        int k = w + rr * 32;
        float4* row = (float4*)(Kb + ((size_t)k << 10));
        float4 v[8];
        float m = -INFINITY;
        #pragma unroll
        for (int j = 0; j < 8; j++) {
            v[j] = row[j * 32 + l];
            m = fmaxf(m, fmaxf(fmaxf(v[j].x, v[j].y), fmaxf(v[j].z, v[j].w)));
        }
        m = warpMax(m);
        float s = 0.0f;
        #pragma unroll
        for (int j = 0; j < 8; j++) {
            v[j].x = exp2_fma(v[j].x - m);
            v[j].y = exp2_fma(v[j].y - m);
            v[j].z = exp2_fma(v[j].z - m);
            v[j].w = exp2_fma(v[j].w - m);
            s += (v[j].x + v[j].y) + (v[j].z + v[j].w);
            row[j * 32 + l] = v[j];
        }
        s = warpSum(s);
        if (l == 0) rs[k] = (1.0f / 65.0f) / s;
    }
    if (t == 0) rs[64] = (1.0f / 65.0f) / 1024.0f;
    __syncthreads();

    const int kg = t >> 8, cg = t & 255;
    const float4* colp = (const float4*)Kb + cg;

    #pragma unroll 1
    for (int it = 0; it < 5; it++) {
        // ---- c-update: thread (kg, cg) covers 16 k-rows x 4 cols, float4 ----
        float4 a = make_float4(0.f, 0.f, 0.f, 0.f);
        #pragma unroll
        for (int k = 0; k < 16; k++) {
            int row = kg * 16 + k;
            float4 v = colp[(size_t)row << 8];
            float rv = rs[row];
            a.x = fmaf(v.x, rv, a.x);
            a.y = fmaf(v.y, rv, a.y);
            a.z = fmaf(v.z, rv, a.z);
            a.w = fmaf(v.w, rv, a.w);
        }
        part[t] = a;
        __syncthreads();
        float sw = 0.0f;
        if (t < 256) {
            float4 p0 = part[t], p1 = part[t + 256];
            float4 p2 = part[t + 512], p3 = part[t + 768];
            float dust = rs[64];
            float4 cv;
            cv.x = (1.0f / 1024.0f) / ((p0.x + p1.x) + (p2.x + p3.x) + dust);
            cv.y = (1.0f / 1024.0f) / ((p0.y + p1.y) + (p2.y + p3.y) + dust);
            cv.z = (1.0f / 1024.0f) / ((p0.z + p1.z) + (p2.z + p3.z) + dust);
            cv.w = (1.0f / 1024.0f) / ((p0.w + p1.w) + (p2.w + p3.w) + dust);
            cs4[t] = cv;
            sw = (cv.x + cv.y) + (cv.z + cv.w);
        }
        sw = warpSum(sw);
        if (l == 0) red[w] = sw;
        __syncthreads();
        if (it < 4) {
            if (t == 0) {
                float s = 0.0f;
                #pragma unroll
                for (int i = 0; i < 8; i++) s += red[i];
                rs[64] = (1.0f / 65.0f) / s;
            }
            // ---- r-update (warp w -> rows w, w+32), float4 ----
            #pragma unroll
            for (int rr = 0; rr < 2; rr++) {
                int k = w + rr * 32;
                const float4* row = (const float4*)(Kb + ((size_t)k << 10));
                float4 d = make_float4(0.f, 0.f, 0.f, 0.f);
                #pragma unroll
                for (int j = 0; j < 8; j++) {
                    float4 rv4 = row[j * 32 + l];
                    float4 c4 = cs4[j * 32 + l];
                    d.x = fmaf(rv4.x, c4.x, d.x);
                    d.y = fmaf(rv4.y, c4.y, d.y);
                    d.z = fmaf(rv4.z, c4.z, d.z);
                    d.w = fmaf(rv4.w, c4.w, d.w);
                }
                float dd = warpSum((d.x + d.y) + (d.z + d.w));
                if (l == 0) rs[k] = (1.0f / 65.0f) / dd;
            }
            __syncthreads();
        }
    }
    if (t < 256) *(float4*)(g_c + b * 1024 + t * 4) = cs4[t];
    if (t < 65) g_r[b * 65 + t] = rs[t];
}

// ---------------------------------------------------------------------------
// gemmC via mma.sync (unchanged from R10).
// ---------------------------------------------------------------------------
#define PSH_HI 0
#define PSH_LO 17408
#define FSH_HI 34816
#define FSH_LO 69632
#define SMC_TOTAL 104448

__global__ __launch_bounds__(256) void gemmC_mma()
{
    extern __shared__ char sm[];
    const uint32_t smu = smem_u32(sm);
    const int b = blockIdx.y, sp = blockIdx.x;
    const int tid = threadIdx.x, wid = tid >> 5, lane = tid & 31;
    const int wr = wid & 1, wc = wid >> 1;
    const int g = lane >> 2, tig = lane & 3;
    const int rl = lane & 15, kh = lane >> 4;
    const int n0 = sp * 128;

    #pragma unroll
    for (int j = 0; j < 8; j++) {
        int e = tid + j * 256;
        int n = e >> 4, u = e & 15;
        uint32_t doff = (uint32_t)(n * 272 + u * 16);
        size_t src = ((size_t)(b * 1024 + n0 + n)) * 128 + u * 8;
        cpasync16(smu + FSH_HI + doff, g_fh + src);
        cpasync16(smu + FSH_LO + doff, g_fl + src);
    }
    CP_COMMIT();

    {
        const int k = tid >> 2, nq = (tid & 3) * 32;
        const float rv = __ldg(&g_r[b * 65 + k]) * 256.0f;
        const float4* Kp = (const float4*)(g_K + ((size_t)(b * 64 + k)) * 1024 + n0 + nq);
        const float4* Cp = (const float4*)(g_c + b * 1024 + n0 + nq);
        char* ph = sm + PSH_HI + (k * 136 + nq) * 2;
        char* pl = sm + PSH_LO + (k * 136 + nq) * 2;
        float psum = 0.0f;
        #pragma unroll
        for (int j = 0; j < 8; j++) {
            float4 kv = Kp[j];
            float4 cv = Cp[j];
            float p0 = kv.x * cv.x * rv, p1 = kv.y * cv.y * rv;
            float p2 = kv.z * cv.z * rv, p3 = kv.w * cv.w * rv;
            psum += (p0 + p1) + (p2 + p3);
            __half h0 = __float2half_rn(p0), h1 = __float2half_rn(p1);
            __half h2 = __float2half_rn(p2), h3 = __float2half_rn(p3);
            *(uint2*)(ph + j * 8) = make_uint2(pack_h2(h0, h1), pack_h2(h2, h3));
            *(uint2*)(pl + j * 8) = make_uint2(
                pack_h2(__float2half_rn(p0 - __half2float(h0)),
                        __float2half_rn(p1 - __half2float(h1))),
                pack_h2(__float2half_rn(p2 - __half2float(h2)),
                        __float2half_rn(p3 - __half2float(h3))));
        }
        psum += __shfl_xor_sync(0xffffffffu, psum, 1);
        psum += __shfl_xor_sync(0xffffffffu, psum, 2);
        if ((tid & 3) == 0)
            g_pspart[(b * 8 + sp) * 64 + k] = psum * (1.0f / 256.0f);
    }
    CP_WAIT0();
    __syncthreads();

    float acc[2][4][4];
    #pragma unroll
    for (int mf = 0; mf < 2; mf++)
        #pragma unroll
        for (int nf = 0; nf < 4; nf++)
            #pragma unroll
            for (int q = 0; q < 4; q++) acc[mf][nf][q] = 0.0f;

    const uint32_t pHiB = smu + PSH_HI + (wr * 32 + rl) * 272 + kh * 16;
    const uint32_t pLoB = pHiB + (PSH_LO - PSH_HI);
    const uint32_t fHiB = smu + FSH_HI + rl * 272 + (wc * 32) * 2 + kh * 16;
    const uint32_t fLoB = fHiB + (FSH_LO - FSH_HI);

    #pragma unroll
    for (int s = 0; s < 8; s++) {
        const uint32_t ko = s * 32;
        const uint32_t fo = s * 16 * 272;
        uint32_t ph[2][4], pl[2][4];
        uint32_t bh0[4], bh1[4], bl0[4], bl1[4];
        ldsm4(ph[0][0], ph[0][1], ph[0][2], ph[0][3], pHiB + ko);
        ldsm4(ph[1][0], ph[1][1], ph[1][2], ph[1][3], pHiB + 16 * 272 + ko);
        ldsm4(pl[0][0], pl[0][1], pl[0][2], pl[0][3], pLoB + ko);
        ldsm4(pl[1][0], pl[1][1], pl[1][2], pl[1][3], pLoB + 16 * 272 + ko);
        ldsm4t(bh0[0], bh0[1], bh0[2], bh0[3], fHiB + fo);
        ldsm4t(bh1[0], bh1[1], bh1[2], bh1[3], fHiB + fo + 32);
        ldsm4t(bl0[0], bl0[1], bl0[2], bl0[3], fLoB + fo);
        ldsm4t(bl1[0], bl1[1], bl1[2], bl1[3], fLoB + fo + 32);

        #pragma unroll
        for (int mf = 0; mf < 2; mf++) {
            mma16816(acc[mf][0], ph[mf][0], ph[mf][1], ph[mf][2], ph[mf][3], bh0[0], bh0[1]);
            mma16816(acc[mf][1], ph[mf][0], ph[mf][1], ph[mf][2], ph[mf][3], bh0[2], bh0[3]);
            mma16816(acc[mf][2], ph[mf][0], ph[mf][1], ph[mf][2], ph[mf][3], bh1[0], bh1[1]);
            mma16816(acc[mf][3], ph[mf][0], ph[mf][1], ph[mf][2], ph[mf][3], bh1[2], bh1[3]);
            mma16816(acc[mf][0], ph[mf][0], ph[mf][1], ph[mf][2], ph[mf][3], bl0[0], bl0[1]);
            mma16816(acc[mf][1], ph[mf][0], ph[mf][1], ph[mf][2], ph[mf][3], bl0[2], bl0[3]);
            mma16816(acc[mf][2], ph[mf][0], ph[mf][1], ph[mf][2], ph[mf][3], bl1[0], bl1[1]);
            mma16816(acc[mf][3], ph[mf][0], ph[mf][1], ph[mf][2], ph[mf][3], bl1[2], bl1[3]);
            mma16816(acc[mf][0], pl[mf][0], pl[mf][1], pl[mf][2], pl[mf][3], bh0[0], bh0[1]);
            mma16816(acc[mf][1], pl[mf][0], pl[mf][1], pl[mf][2], pl[mf][3], bh0[2], bh0[3]);
            mma16816(acc[mf][2], pl[mf][0], pl[mf][1], pl[mf][2], pl[mf][3], bh1[0], bh1[1]);
            mma16816(acc[mf][3], pl[mf][0], pl[mf][1], pl[mf][2], pl[mf][3], bh1[2], bh1[3]);
        }
    }

    const float inv256 = 1.0f / 256.0f;
    #pragma unroll
    for (int mf = 0; mf < 2; mf++) {
        #pragma unroll
        for (int nf = 0; nf < 4; nf++) {
            int k0 = wr * 32 + mf * 16 + g;
            int c = wc * 32 + nf * 8 + tig * 2;
            float* base = g_vpart + ((size_t)(b * 8 + sp) * 64) * 128;
            *(float2*)(base + (size_t)k0 * 128 + c) =
                make_float2(acc[mf][nf][0] * inv256, acc[mf][nf][1] * inv256);
            *(float2*)(base + (size_t)(k0 + 8) * 128 + c) =
                make_float2(acc[mf][nf][2] * inv256, acc[mf][nf][3] * inv256);
        }
    }
}

// ----- finalK: split-K reduce + anchors + t concat + L2 normalize ------------
__global__ __launch_bounds__(1024) void finalK(
    const float* __restrict__ anchors, float* __restrict__ out)
{
    const int b = blockIdx.x, t = threadIdx.x;
    float* orow = out + (size_t)b * 8448;
    float ss = 0.0f;

    #pragma unroll
    for (int j = 0; j < 8; j++) {
        int e = t + j * 1024;
        int k = e >> 7, c = e & 127;
        float s2 = 0.0f, sps = 0.0f;
        #pragma unroll
        for (int sp = 0; sp < 8; sp++) {
            s2  += g_vpart[(((size_t)(b * 8 + sp) * 64) + k) * 128 + c];
            sps += g_pspart[(b * 8 + sp) * 64 + k];
        }
        float val = 2.0f * s2 - sps * anchors[k * 128 + c];
        orow[256 + e] = val;
        ss += val * val;
    }
    if (t < 256) {
        float tv = g_t[b * 256 + t];
        orow[t] = tv;
        ss += tv * tv;
    }

    __shared__ float red[32];
    __shared__ float s_inv;
    float w = warpSum(ss);
    if ((t & 31) == 0) red[t >> 5] = w;
    __syncthreads();
    if (t < 32) {
        float v = red[t];
        v = warpSum(v);
        if (t == 0) s_inv = 1.0f / fmaxf(sqrtf(v), 1e-12f);
    }
    __syncthreads();
    const float inv = s_inv;
    for (int idx = t; idx < 8448; idx += 1024) orow[idx] *= inv;
}

// ---------------------------------------------------------------------------
extern "C" void kernel_launch(void* const* d_in, const int* in_sizes, int n_in,
                              void* d_out, int out_size)
{
    const float* x       = (const float*)d_in[0];
    const float* Wf      = (const float*)d_in[1];
    const float* bf      = (const float*)d_in[2];
    const float* Ws      = (const float*)d_in[3];
    const float* bs      = (const float*)d_in[4];
    const float* Wt      = (const float*)d_in[5];
    const float* bt      = (const float*)d_in[6];
    const float* anchors = (const float*)d_in[7];
    // d_in[8] = dust_bin: constant row shift, cancels in the transport plan.
    const float* sharp   = (const float*)d_in[9];
    float* out = (float*)d_out;

    static int smem_set = 0;
    if (!smem_set) {
        cudaFuncSetAttribute(gemmA_mma, cudaFuncAttributeMaxDynamicSharedMemorySize, SM_TOTAL);
        cudaFuncSetAttribute(gemmC_mma, cudaFuncAttributeMaxDynamicSharedMemorySize, SMC_TOTAL);
        smem_set = 1;
    }

    prep<<<608, 256>>>(Wf, Ws, x, Wt, bt);
    gemmA_mma<<<dim3(8, 32), 512, SM_TOTAL>>>(x, bf, bs, sharp);
    sinkhorn<<<32, 1024>>>();
    gemmC_mma<<<dim3(8, 32), 256, SMC_TOTAL>>>();
    finalK<<<32, 1024>>>(anchors, out);
}

// round 12
// speedup vs baseline: 1.0346x; 1.0346x over previous
#include <cuda_runtime.h>
#include <cuda_fp16.h>
#include <math.h>
#include <stdint.h>

#define LOG2E_F 1.4426950408889634f

// ---------------- scratch (static device globals; no allocs) ----------------
__device__ float  g_K[32 * 64 * 1024];        // M' -> K~ (in place)       8 MB
__device__ float  g_r[32 * 65];               // Sinkhorn row scalings
__device__ float  g_c[32 * 1024];             // Sinkhorn col scalings
__device__ float  g_vpart[32 * 8 * 64 * 128]; // split-K partials of p@f
__device__ float  g_pspart[32 * 8 * 64];      // split-K partials of rowsum(p)
__device__ float  g_t[32 * 256];              // t = x0 @ Wt + bt
__device__ __half g_Bhi[192 * 768];           // (W^T * 256) hi, [n][k]
__device__ __half g_Blo[192 * 768];           // (W^T * 256) lo
__device__ __half g_fh[32 * 1024 * 128];      // f (half)                 8 MB

// ------------------------------- helpers -------------------------------------
__device__ __forceinline__ float warpSum(float v) {
    #pragma unroll
    for (int o = 16; o > 0; o >>= 1) v += __shfl_xor_sync(0xffffffffu, v, o);
    return v;
}
__device__ __forceinline__ float warpMax(float v) {
    #pragma unroll
    for (int o = 16; o > 0; o >>= 1) v = fmaxf(v, __shfl_xor_sync(0xffffffffu, v, o));
    return v;
}
// exp2 on the FMA pipe (x <= 0 here). deg-5 Taylor, rel err ~2e-6.
__device__ __forceinline__ float exp2_fma(float x) {
    x = fmaxf(x, -125.0f);
    int   ni = __float2int_rn(x);
    float f  = x - (float)ni;
    float p  = 1.3333558e-3f;
    p = fmaf(p, f, 9.6181290e-3f);
    p = fmaf(p, f, 5.5504109e-2f);
    p = fmaf(p, f, 2.4022651e-1f);
    p = fmaf(p, f, 6.9314718e-1f);
    p = fmaf(p, f, 1.0f);
    return p * __int_as_float((ni + 127) << 23);
}
__device__ __forceinline__ void mma16816(float* d, uint32_t a0, uint32_t a1,
                                         uint32_t a2, uint32_t a3,
                                         uint32_t b0, uint32_t b1) {
    asm volatile(
        "mma.sync.aligned.m16n8k16.row.col.f32.f16.f16.f32 "
        "{%0,%1,%2,%3}, {%4,%5,%6,%7}, {%8,%9}, {%0,%1,%2,%3};"
        : "+f"(d[0]), "+f"(d[1]), "+f"(d[2]), "+f"(d[3])
        : "r"(a0), "r"(a1), "r"(a2), "r"(a3), "r"(b0), "r"(b1));
}
__device__ __forceinline__ void ldsm4(uint32_t& r0, uint32_t& r1,
                                      uint32_t& r2, uint32_t& r3, uint32_t a) {
    asm volatile("ldmatrix.sync.aligned.m8n8.x4.shared.b16 {%0,%1,%2,%3}, [%4];"
                 : "=r"(r0), "=r"(r1), "=r"(r2), "=r"(r3) : "r"(a));
}
__device__ __forceinline__ void ldsm4t(uint32_t& r0, uint32_t& r1,
                                       uint32_t& r2, uint32_t& r3, uint32_t a) {
    asm volatile("ldmatrix.sync.aligned.m8n8.x4.trans.shared.b16 {%0,%1,%2,%3}, [%4];"
                 : "=r"(r0), "=r"(r1), "=r"(r2), "=r"(r3) : "r"(a));
}
__device__ __forceinline__ uint32_t pack_h2(__half a, __half b) {
    __half2 h = __halves2half2(a, b);
    return *(uint32_t*)&h;
}
__device__ __forceinline__ uint32_t smem_u32(const void* p) {
    uint32_t a;
    asm("{ .reg .u64 t; cvta.to.shared.u64 t, %1; cvt.u32.u64 %0, t; }" : "=r"(a) : "l"(p));
    return a;
}
__device__ __forceinline__ void cpasync16(uint32_t dst, const void* src) {
    asm volatile("cp.async.cg.shared.global [%0], [%1], 16;" :: "r"(dst), "l"(src));
}
#define CP_COMMIT() asm volatile("cp.async.commit_group;" ::: "memory")
#define CP_WAIT0()  asm volatile("cp.async.wait_group 0;" ::: "memory")

// ---- prep: fused W-split (blocks 0..575) + t-GEMM (blocks 576..607) ---------
__global__ __launch_bounds__(256) void prep(
    const float* __restrict__ Wf, const float* __restrict__ Ws,
    const float* __restrict__ x, const float* __restrict__ Wt,
    const float* __restrict__ bt)
{
    const int blk = blockIdx.x;
    __shared__ float xs[768];
    if (blk < 384) {
        int i = blk * 256 + threadIdx.x;            // 128*768
        int n = i / 768, k = i - n * 768;
        float v = Wf[(size_t)k * 128 + n] * 256.0f;
        __half hi = __float2half_rn(v);
        g_Bhi[i] = hi;
        g_Blo[i] = __float2half_rn(v - __half2float(hi));
    } else if (blk < 576) {
        int i = (blk - 384) * 256 + threadIdx.x;    // 64*768
        int n = i / 768, k = i - n * 768;
        float v = Ws[(size_t)k * 64 + n] * 256.0f;
        __half hi = __float2half_rn(v);
        g_Bhi[128 * 768 + i] = hi;
        g_Blo[128 * 768 + i] = __float2half_rn(v - __half2float(hi));
    } else {
        const int b = blk - 576;
        const int c = threadIdx.x;
        for (int i = c; i < 768; i += 256) xs[i] = x[(size_t)b * 1025 * 768 + i];
        __syncthreads();
        float acc = bt[c];
        #pragma unroll 8
        for (int d = 0; d < 768; d++) acc = fmaf(xs[d], Wt[(size_t)d * 256 + c], acc);
        g_t[b * 256 + c] = acc;
    }
}

// ---------------------------------------------------------------------------
// gemmA via mma.sync + ldmatrix, double-buffered A and B smem.
// f cols: 1-term, stored as single fp16. s cols: 3-term into g_K.
// ---------------------------------------------------------------------------
#define A_MAT  18432
#define SMA_HI(buf) ((buf) * (2 * A_MAT))
#define SMA_LO_OFF A_MAT
#define B_HI_SZ 27648
#define B_LOS_SZ 9216
#define B_BUF (B_HI_SZ + B_LOS_SZ)
#define SMB_HI(buf) (4 * A_MAT + (buf) * B_BUF)
#define SMB_LOS_OFF B_HI_SZ
#define SM_TOTAL (4 * A_MAT + 2 * B_BUF)      // 147456 B

__global__ __launch_bounds__(512) void gemmA_mma(
    const float* __restrict__ x, const float* __restrict__ bf,
    const float* __restrict__ bs, const float* __restrict__ sharp)
{
    extern __shared__ char sm[];
    const uint32_t smu = smem_u32(sm);
    const int tid = threadIdx.x, wid = tid >> 5, lane = tid & 31;
    const int b = blockIdx.y, nt = blockIdx.x;
    const int wr = wid & 3, wc = wid >> 2;
    const int g = lane >> 2, tig = lane & 3;

    const int rl = lane & 15, kh = lane >> 4;
    const uint32_t aOff   = (uint32_t)((wr * 32 + rl) * 144 + kh * 16);
    const uint32_t bfOff  = (uint32_t)((wc * 32 + rl) * 144 + kh * 16);
    const uint32_t bshOff = (uint32_t)((128 + wc * 16 + rl) * 144 + kh * 16);
    const uint32_t bslOff = (uint32_t)(SMB_LOS_OFF + (wc * 16 + rl) * 144 + kh * 16);

    const float* A = x + (size_t)b * 1025 * 768 + 768 + (size_t)nt * 128 * 768;
    const int am = tid >> 2, akb = (tid & 3) * 16;
    const float* aptr = A + (size_t)am * 768 + akb;
    const uint32_t cvtOff = (uint32_t)(am * 144 + akb * 2);

    float acc[2][6][4];
    float accS2[2][2][4];
    #pragma unroll
    for (int mf = 0; mf < 2; mf++) {
        #pragma unroll
        for (int nf = 0; nf < 6; nf++)
            #pragma unroll
            for (int q = 0; q < 4; q++) acc[mf][nf][q] = 0.0f;
        #pragma unroll
        for (int nf = 0; nf < 2; nf++)
            #pragma unroll
            for (int q = 0; q < 4; q++) accS2[mf][nf][q] = 0.0f;
    }

    float4 aPre[4];
    uint4 h0, h1, l0, l1;

    #define CONVERT_A(WBUF)                                                     \
    do {                                                                        \
        char* dhi = sm + SMA_HI(WBUF) + cvtOff;                                 \
        _Pragma("unroll")                                                       \
        for (int i = 0; i < 4; i++) {                                           \
            float4 v = aPre[i];                                                 \
            __half hx = __float2half_rn(v.x), hy = __float2half_rn(v.y);        \
            __half hz = __float2half_rn(v.z), hw = __float2half_rn(v.w);        \
            __half lx = __float2half_rn(v.x - __half2float(hx));                \
            __half ly = __float2half_rn(v.y - __half2float(hy));                \
            __half lz = __float2half_rn(v.z - __half2float(hz));                \
            __half lw = __float2half_rn(v.w - __half2float(hw));                \
            uint32_t hqa = pack_h2(hx, hy), hqb = pack_h2(hz, hw);              \
            uint32_t lqa = pack_h2(lx, ly), lqb = pack_h2(lz, lw);              \
            if (i == 0) { h0.x = hqa; h0.y = hqb; l0.x = lqa; l0.y = lqb; }     \
            else if (i == 1) { h0.z = hqa; h0.w = hqb; l0.z = lqa; l0.w = lqb; }\
            else if (i == 2) { h1.x = hqa; h1.y = hqb; l1.x = lqa; l1.y = lqb; }\
            else { h1.z = hqa; h1.w = hqb; l1.z = lqa; l1.w = lqb; }            \
        }                                                                       \
        *(uint4*)(dhi) = h0;  *(uint4*)(dhi + 16) = h1;                         \
        *(uint4*)(dhi + SMA_LO_OFF) = l0; *(uint4*)(dhi + SMA_LO_OFF + 16) = l1;\
    } while (0)

    #define FETCH_B(CH, WBUF)                                                   \
    do {                                                                        \
        const int kk0 = (CH) * 64;                                              \
        _Pragma("unroll")                                                       \
        for (int j = 0; j < 3; j++) {                                           \
            int e = tid + j * 512;                                              \
            int n = e >> 3, u = e & 7;                                          \
            cpasync16(smu + SMB_HI(WBUF) + (uint32_t)(n * 144 + u * 16),        \
                      g_Bhi + (size_t)n * 768 + kk0 + u * 8);                   \
        }                                                                       \
        {                                                                       \
            int n = tid >> 3, u = tid & 7;                                      \
            if (n < 64)                                                         \
                cpasync16(smu + SMB_HI(WBUF) + SMB_LOS_OFF +                    \
                          (uint32_t)(n * 144 + u * 16),                         \
                          g_Blo + (size_t)(128 + n) * 768 + kk0 + u * 8);       \
        }                                                                       \
        CP_COMMIT();                                                            \
    } while (0)

    // ---- prologue ----
    #pragma unroll
    for (int i = 0; i < 4; i++) aPre[i] = *(const float4*)(aptr + i * 4);
    FETCH_B(0, 0);
    CONVERT_A(0);
    #pragma unroll
    for (int i = 0; i < 4; i++) aPre[i] = *(const float4*)(aptr + 64 + i * 4);
    CP_WAIT0();
    __syncthreads();

    #pragma unroll 1
    for (int ch = 0; ch < 12; ch++) {
        const int buf = ch & 1;
        if (ch < 11) {
            FETCH_B(ch + 1, buf ^ 1);
            CONVERT_A(buf ^ 1);
            if (ch < 10) {
                const int k2 = (ch + 2) * 64;
                #pragma unroll
                for (int i = 0; i < 4; i++) aPre[i] = *(const float4*)(aptr + k2 + i * 4);
            }
        }

        const uint32_t aHiB = smu + SMA_HI(buf) + aOff;
        const uint32_t aLoB = aHiB + SMA_LO_OFF;
        const uint32_t bHfB = smu + SMB_HI(buf) + bfOff;
        const uint32_t bHsB = smu + SMB_HI(buf) + bshOff;
        const uint32_t bLsB = smu + SMB_HI(buf) + bslOff;
        #pragma unroll
        for (int ks = 0; ks < 4; ks++) {
            const uint32_t ko = ks * 32;
            uint32_t ah[2][4], al[2][4];
            uint32_t bsh0, bsh1, bsh2, bsh3, bsl0, bsl1, bsl2, bsl3;
            uint32_t bfa[4], bfb[4];
            ldsm4(ah[0][0], ah[0][1], ah[0][2], ah[0][3], aHiB + ko);
            ldsm4(ah[1][0], ah[1][1], ah[1][2], ah[1][3], aHiB + 16 * 144 + ko);
            ldsm4(bsh0, bsh1, bsh2, bsh3, bHsB + ko);
            ldsm4(al[0][0], al[0][1], al[0][2], al[0][3], aLoB + ko);
            ldsm4(al[1][0], al[1][1], al[1][2], al[1][3], aLoB + 16 * 144 + ko);
            ldsm4(bsl0, bsl1, bsl2, bsl3, bLsB + ko);
            ldsm4(bfa[0], bfa[1], bfa[2], bfa[3], bHfB + ko);
            ldsm4(bfb[0], bfb[1], bfb[2], bfb[3], bHfB + 16 * 144 + ko);

            mma16816(acc[0][4], ah[0][0], ah[0][1], ah[0][2], ah[0][3], bsh0, bsh2);
            mma16816(acc[0][5], ah[0][0], ah[0][1], ah[0][2], ah[0][3], bsh1, bsh3);
            mma16816(acc[1][4], ah[1][0], ah[1][1], ah[1][2], ah[1][3], bsh0, bsh2);
            mma16816(acc[1][5], ah[1][0], ah[1][1], ah[1][2], ah[1][3], bsh1, bsh3);
            mma16816(acc[0][0], ah[0][0], ah[0][1], ah[0][2], ah[0][3], bfa[0], bfa[2]);
            mma16816(acc[0][1], ah[0][0], ah[0][1], ah[0][2], ah[0][3], bfa[1], bfa[3]);
            mma16816(acc[1][0], ah[1][0], ah[1][1], ah[1][2], ah[1][3], bfa[0], bfa[2]);
            mma16816(acc[1][1], ah[1][0], ah[1][1], ah[1][2], ah[1][3], bfa[1], bfa[3]);
            mma16816(accS2[0][0], ah[0][0], ah[0][1], ah[0][2], ah[0][3], bsl0, bsl2);
            mma16816(accS2[0][1], ah[0][0], ah[0][1], ah[0][2], ah[0][3], bsl1, bsl3);
            mma16816(accS2[1][0], ah[1][0], ah[1][1], ah[1][2], ah[1][3], bsl0, bsl2);
            mma16816(accS2[1][1], ah[1][0], ah[1][1], ah[1][2], ah[1][3], bsl1, bsl3);
            mma16816(acc[0][2], ah[0][0], ah[0][1], ah[0][2], ah[0][3], bfb[0], bfb[2]);
            mma16816(acc[0][3], ah[0][0], ah[0][1], ah[0][2], ah[0][3], bfb[1], bfb[3]);
            mma16816(acc[1][2], ah[1][0], ah[1][1], ah[1][2], ah[1][3], bfb[0], bfb[2]);
            mma16816(acc[1][3], ah[1][0], ah[1][1], ah[1][2], ah[1][3], bfb[1], bfb[3]);
            mma16816(acc[0][4], al[0][0], al[0][1], al[0][2], al[0][3], bsh0, bsh2);
            mma16816(acc[0][5], al[0][0], al[0][1], al[0][2], al[0][3], bsh1, bsh3);
            mma16816(acc[1][4], al[1][0], al[1][1], al[1][2], al[1][3], bsh0, bsh2);
            mma16816(acc[1][5], al[1][0], al[1][1], al[1][2], al[1][3], bsh1, bsh3);
        }
        if (ch < 11) CP_WAIT0();
        __syncthreads();
    }

    // ---------------------------- epilogue ----------------------------------
    const float inv256 = 1.0f / 256.0f;
    const float scl = sharp[0] * 10.0f * LOG2E_F;
    #pragma unroll
    for (int mf = 0; mf < 2; mf++) {
        #pragma unroll
        for (int nf = 0; nf < 4; nf++) {
            int c = wc * 32 + nf * 8 + tig * 2;
            int r0 = nt * 128 + wr * 32 + mf * 16 + g;
            int r1 = r0 + 8;
            float b0 = __ldg(bf + c), b1 = __ldg(bf + c + 1);
            float f00 = fmaf(acc[mf][nf][0], inv256, b0);
            float f01 = fmaf(acc[mf][nf][1], inv256, b1);
            float f10 = fmaf(acc[mf][nf][2], inv256, b0);
            float f11 = fmaf(acc[mf][nf][3], inv256, b1);
            size_t i0 = ((size_t)(b * 1024 + r0)) * 128 + c;
            size_t i1 = ((size_t)(b * 1024 + r1)) * 128 + c;
            *(uint32_t*)(g_fh + i0) = pack_h2(__float2half_rn(f00), __float2half_rn(f01));
            *(uint32_t*)(g_fh + i1) = pack_h2(__float2half_rn(f10), __float2half_rn(f11));
        }
        #pragma unroll
        for (int nf = 4; nf < 6; nf++) {
            int k = wc * 16 + (nf - 4) * 8 + tig * 2;
            int r0 = nt * 128 + wr * 32 + mf * 16 + g;
            int r1 = r0 + 8;
            float b0 = __ldg(bs + k), b1 = __ldg(bs + k + 1);
            float* K0 = g_K + ((size_t)(b * 64 + k)) * 1024;
            float* K1 = g_K + ((size_t)(b * 64 + k + 1)) * 1024;
            float d0 = acc[mf][nf][0] + accS2[mf][nf - 4][0];
            float d1 = acc[mf][nf][1] + accS2[mf][nf - 4][1];
            float d2 = acc[mf][nf][2] + accS2[mf][nf - 4][2];
            float d3 = acc[mf][nf][3] + accS2[mf][nf - 4][3];
            K0[r0] = fmaf(d0, inv256, b0) * scl;
            K1[r0] = fmaf(d1, inv256, b1) * scl;
            K0[r1] = fmaf(d2, inv256, b0) * scl;
            K1[r1] = fmaf(d3, inv256, b1) * scl;
        }
    }
}

// ------ sinkhorn: fused exp phase + 5 c-updates + 4 r-updates (R10 ver) ------
__global__ __launch_bounds__(1024) void sinkhorn()
{
    const int b = blockIdx.x;
    const int t = threadIdx.x, w = t >> 5, l = t & 31;
    __shared__ float cs[1024];
    __shared__ float rs[72];
    __shared__ float red[32];
    float* Kb = g_K + ((size_t)b << 16);

    // ---- phase 1: rowmax + exp2 + rowsum (warp w -> rows w, w+32) ----
    #pragma unroll
    for (int rr = 0; rr < 2; rr++) {
        int k = w + rr * 32;
        float* row = Kb + ((size_t)k << 10);
        float m = -INFINITY;
        #pragma unroll 8
        for (int n = l; n < 1024; n += 32) m = fmaxf(m, row[n]);
        m = warpMax(m);
        float s = 0.0f;
        #pragma unroll 8
        for (int n = l; n < 1024; n += 32) {
            float e = exp2_fma(row[n] - m);
            row[n] = e;
            s += e;
        }
        s = warpSum(s);
        if (l == 0) rs[k] = (1.0f / 65.0f) / s;
    }
    if (t == 0) rs[64] = (1.0f / 65.0f) / 1024.0f;
    __syncthreads();

    // ---- iterations ----
    #pragma unroll 1
    for (int it = 0; it < 5; it++) {
        const float* col = Kb + t;
        float a0 = rs[64], a1 = 0.f, a2 = 0.f, a3 = 0.f;
        float a4 = 0.f, a5 = 0.f, a6 = 0.f, a7 = 0.f;
        #pragma unroll
        for (int k = 0; k < 64; k += 8) {
            a0 = fmaf(col[(size_t)(k + 0) << 10], rs[k + 0], a0);
            a1 = fmaf(col[(size_t)(k + 1) << 10], rs[k + 1], a1);
            a2 = fmaf(col[(size_t)(k + 2) << 10], rs[k + 2], a2);
            a3 = fmaf(col[(size_t)(k + 3) << 10], rs[k + 3], a3);
            a4 = fmaf(col[(size_t)(k + 4) << 10], rs[k + 4], a4);
            a5 = fmaf(col[(size_t)(k + 5) << 10], rs[k + 5], a5);
            a6 = fmaf(col[(size_t)(k + 6) << 10], rs[k + 6], a6);
            a7 = fmaf(col[(size_t)(k + 7) << 10], rs[k + 7], a7);
        }
        float cv = (1.0f / 1024.0f) /
                   (((a0 + a1) + (a2 + a3)) + ((a4 + a5) + (a6 + a7)));
        cs[t] = cv;
        float sw = warpSum(cv);
        if (l == 0) red[w] = sw;
        __syncthreads();
        if (it < 4) {
            if (t == 0) {
                float s = 0.0f;
                #pragma unroll
                for (int i = 0; i < 32; i++) s += red[i];
                rs[64] = (1.0f / 65.0f) / s;
            }
            #pragma unroll
            for (int rr = 0; rr < 2; rr++) {
                int k = w + rr * 32;
                const float* row = Kb + ((size_t)k << 10);
                float d0 = 0.f, d1 = 0.f, d2 = 0.f, d3 = 0.f;
                float d4 = 0.f, d5 = 0.f, d6 = 0.f, d7 = 0.f;
                #pragma unroll
                for (int n0 = 0; n0 < 1024; n0 += 256) {
                    d0 = fmaf(row[n0 + l],        cs[n0 + l],        d0);
                    d1 = fmaf(row[n0 + l + 32],   cs[n0 + l + 32],   d1);
                    d2 = fmaf(row[n0 + l + 64],   cs[n0 + l + 64],   d2);
                    d3 = fmaf(row[n0 + l + 96],   cs[n0 + l + 96],   d3);
                    d4 = fmaf(row[n0 + l + 128],  cs[n0 + l + 128],  d4);
                    d5 = fmaf(row[n0 + l + 160],  cs[n0 + l + 160],  d5);
                    d6 = fmaf(row[n0 + l + 192],  cs[n0 + l + 192],  d6);
                    d7 = fmaf(row[n0 + l + 224],  cs[n0 + l + 224],  d7);
                }
                float d = warpSum((((d0 + d1) + (d2 + d3)) + ((d4 + d5) + (d6 + d7))));
                if (l == 0) rs[k] = (1.0f / 65.0f) / d;
            }
            __syncthreads();
        }
    }
    g_c[b * 1024 + t] = cs[t];
    if (t < 65) g_r[b * 65 + t] = rs[t];
}

// ---------------------------------------------------------------------------
// gemmC via mma.sync, single-term fp16 (p_hi x f_hi). 51 KB smem -> 2 CTA/SM.
// ---------------------------------------------------------------------------
#define PSH_HI 0
#define FSH_HI 17408
#define SMC_TOTAL (17408 + 34816)   // 52224

__global__ __launch_bounds__(256) void gemmC_mma()
{
    extern __shared__ char sm[];
    const uint32_t smu = smem_u32(sm);
    const int b = blockIdx.y, sp = blockIdx.x;
    const int tid = threadIdx.x, wid = tid >> 5, lane = tid & 31;
    const int wr = wid & 1, wc = wid >> 1;
    const int g = lane >> 2, tig = lane & 3;
    const int rl = lane & 15, kh = lane >> 4;
    const int n0 = sp * 128;

    // ---- fill f tile via cp.async ----
    #pragma unroll
    for (int j = 0; j < 8; j++) {
        int e = tid + j * 256;
        int n = e >> 4, u = e & 15;
        uint32_t doff = (uint32_t)(n * 272 + u * 16);
        size_t src = ((size_t)(b * 1024 + n0 + n)) * 128 + u * 8;
        cpasync16(smu + FSH_HI + doff, g_fh + src);
    }
    CP_COMMIT();

    // ---- build p (scaled x256) into smem fp16 + rowsum ----
    {
        const int k = tid >> 2, nq = (tid & 3) * 32;
        const float rv = __ldg(&g_r[b * 65 + k]) * 256.0f;
        const float4* Kp = (const float4*)(g_K + ((size_t)(b * 64 + k)) * 1024 + n0 + nq);
        const float4* Cp = (const float4*)(g_c + b * 1024 + n0 + nq);
        char* ph = sm + PSH_HI + (k * 136 + nq) * 2;
        float psum = 0.0f;
        #pragma unroll
        for (int j = 0; j < 8; j++) {
            float4 kv = Kp[j];
            float4 cv = Cp[j];
            float p0 = kv.x * cv.x * rv, p1 = kv.y * cv.y * rv;
            float p2 = kv.z * cv.z * rv, p3 = kv.w * cv.w * rv;
            psum += (p0 + p1) + (p2 + p3);
            *(uint2*)(ph + j * 8) = make_uint2(
                pack_h2(__float2half_rn(p0), __float2half_rn(p1)),
                pack_h2(__float2half_rn(p2), __float2half_rn(p3)));
        }
        psum += __shfl_xor_sync(0xffffffffu, psum, 1);
        psum += __shfl_xor_sync(0xffffffffu, psum, 2);
        if ((tid & 3) == 0)
            g_pspart[(b * 8 + sp) * 64 + k] = psum * (1.0f / 256.0f);
    }
    CP_WAIT0();
    __syncthreads();

    // ---- MMA: M=64 (k), N=128 (c), K=128 (n), single term ----
    float acc[2][4][4];
    #pragma unroll
    for (int mf = 0; mf < 2; mf++)
        #pragma unroll
        for (int nf = 0; nf < 4; nf++)
            #pragma unroll
            for (int q = 0; q < 4; q++) acc[mf][nf][q] = 0.0f;

    const uint32_t pHiB = smu + PSH_HI + (wr * 32 + rl) * 272 + kh * 16;
    const uint32_t fHiB = smu + FSH_HI + rl * 272 + (wc * 32) * 2 + kh * 16;

    #pragma unroll
    for (int s = 0; s < 8; s++) {
        const uint32_t ko = s * 32;
        const uint32_t fo = s * 16 * 272;
        uint32_t ph[2][4];
        uint32_t bh0[4], bh1[4];
        ldsm4(ph[0][0], ph[0][1], ph[0][2], ph[0][3], pHiB + ko);
        ldsm4(ph[1][0], ph[1][1], ph[1][2], ph[1][3], pHiB + 16 * 272 + ko);
        ldsm4t(bh0[0], bh0[1], bh0[2], bh0[3], fHiB + fo);
        ldsm4t(bh1[0], bh1[1], bh1[2], bh1[3], fHiB + fo + 32);

        #pragma unroll
        for (int mf = 0; mf < 2; mf++) {
            mma16816(acc[mf][0], ph[mf][0], ph[mf][1], ph[mf][2], ph[mf][3], bh0[0], bh0[1]);
            mma16816(acc[mf][1], ph[mf][0], ph[mf][1], ph[mf][2], ph[mf][3], bh0[2], bh0[3]);
            mma16816(acc[mf][2], ph[mf][0], ph[mf][1], ph[mf][2], ph[mf][3], bh1[0], bh1[1]);
            mma16816(acc[mf][3], ph[mf][0], ph[mf][1], ph[mf][2], ph[mf][3], bh1[2], bh1[3]);
        }
    }

    // ---- epilogue: vpart = acc / 256 ----
    const float inv256 = 1.0f / 256.0f;
    #pragma unroll
    for (int mf = 0; mf < 2; mf++) {
        #pragma unroll
        for (int nf = 0; nf < 4; nf++) {
            int k0 = wr * 32 + mf * 16 + g;
            int c = wc * 32 + nf * 8 + tig * 2;
            float* base = g_vpart + ((size_t)(b * 8 + sp) * 64) * 128;
            *(float2*)(base + (size_t)k0 * 128 + c) =
                make_float2(acc[mf][nf][0] * inv256, acc[mf][nf][1] * inv256);
            *(float2*)(base + (size_t)(k0 + 8) * 128 + c) =
                make_float2(acc[mf][nf][2] * inv256, acc[mf][nf][3] * inv256);
        }
    }
}

// ----- finalK: split-K reduce + anchors + t concat + L2 normalize ------------
__global__ __launch_bounds__(1024) void finalK(
    const float* __restrict__ anchors, float* __restrict__ out)
{
    const int b = blockIdx.x, t = threadIdx.x;
    float* orow = out + (size_t)b * 8448;
    float ss = 0.0f;

    #pragma unroll
    for (int j = 0; j < 8; j++) {
        int e = t + j * 1024;
        int k = e >> 7, c = e & 127;
        float s2 = 0.0f, sps = 0.0f;
        #pragma unroll
        for (int sp = 0; sp < 8; sp++) {
            s2  += g_vpart[(((size_t)(b * 8 + sp) * 64) + k) * 128 + c];
            sps += g_pspart[(b * 8 + sp) * 64 + k];
        }
        float val = 2.0f * s2 - sps * anchors[k * 128 + c];
        orow[256 + e] = val;
        ss += val * val;
    }
    if (t < 256) {
        float tv = g_t[b * 256 + t];
        orow[t] = tv;
        ss += tv * tv;
    }

    __shared__ float red[32];
    __shared__ float s_inv;
    float w = warpSum(ss);
    if ((t & 31) == 0) red[t >> 5] = w;
    __syncthreads();
    if (t < 32) {
        float v = red[t];
        v = warpSum(v);
        if (t == 0) s_inv = 1.0f / fmaxf(sqrtf(v), 1e-12f);
    }
    __syncthreads();
    const float inv = s_inv;
    for (int idx = t; idx < 8448; idx += 1024) orow[idx] *= inv;
}

// ---------------------------------------------------------------------------
extern "C" void kernel_launch(void* const* d_in, const int* in_sizes, int n_in,
                              void* d_out, int out_size)
{
    const float* x       = (const float*)d_in[0];
    const float* Wf      = (const float*)d_in[1];
    const float* bf      = (const float*)d_in[2];
    const float* Ws      = (const float*)d_in[3];
    const float* bs      = (const float*)d_in[4];
    const float* Wt      = (const float*)d_in[5];
    const float* bt      = (const float*)d_in[6];
    const float* anchors = (const float*)d_in[7];
    // d_in[8] = dust_bin: constant row shift, cancels in the transport plan.
    const float* sharp   = (const float*)d_in[9];
    float* out = (float*)d_out;

    static int smem_set = 0;
    if (!smem_set) {
        cudaFuncSetAttribute(gemmA_mma, cudaFuncAttributeMaxDynamicSharedMemorySize, SM_TOTAL);
        cudaFuncSetAttribute(gemmC_mma, cudaFuncAttributeMaxDynamicSharedMemorySize, SMC_TOTAL);
        smem_set = 1;
    }

    prep<<<608, 256>>>(Wf, Ws, x, Wt, bt);
    gemmA_mma<<<dim3(8, 32), 512, SM_TOTAL>>>(x, bf, bs, sharp);
    sinkhorn<<<32, 1024>>>();
    gemmC_mma<<<dim3(8, 32), 256, SMC_TOTAL>>>();
    finalK<<<32, 1024>>>(anchors, out);
}

// round 14
// speedup vs baseline: 1.0578x; 1.0224x over previous
#include <cuda_runtime.h>
#include <cuda_fp16.h>
#include <cuda_bf16.h>
#include <math.h>
#include <stdint.h>

#define LOG2E_F 1.4426950408889634f

// ---------------- scratch (static device globals; no allocs) ----------------
__device__ float  g_K[32 * 64 * 1024];        // M' (fp32, pre-exp)        8 MB
__device__ __nv_bfloat16 g_Kb[32 * 64 * 1024];// K~ = exp2(M'-max), bf16   4 MB
__device__ float  g_r[32 * 65];               // Sinkhorn row scalings
__device__ float  g_c[32 * 1024];             // Sinkhorn col scalings
__device__ float  g_vpart[32 * 8 * 64 * 128]; // split-K partials of p@f
__device__ float  g_pspart[32 * 8 * 64];      // split-K partials of rowsum(p)
__device__ float  g_ssp[32 * 8];              // per-(b,sp) sumsq partials
__device__ float  g_t[32 * 256];              // t = x0 @ Wt + bt
__device__ __half g_Bhi[192 * 768];           // (W^T * 256) hi, [n][k]
__device__ __half g_Blo[192 * 768];           // (W^T * 256) lo
__device__ __half g_fh[32 * 1024 * 128];      // f (half)                 8 MB

// ------------------------------- helpers -------------------------------------
__device__ __forceinline__ float warpSum(float v) {
    #pragma unroll
    for (int o = 16; o > 0; o >>= 1) v += __shfl_xor_sync(0xffffffffu, v, o);
    return v;
}
__device__ __forceinline__ float warpMax(float v) {
    #pragma unroll
    for (int o = 16; o > 0; o >>= 1) v = fmaxf(v, __shfl_xor_sync(0xffffffffu, v, o));
    return v;
}
// exp2 on the FMA pipe (x <= 0 here). deg-5 Taylor, rel err ~2e-6.
__device__ __forceinline__ float exp2_fma(float x) {
    x = fmaxf(x, -125.0f);
    int   ni = __float2int_rn(x);
    float f  = x - (float)ni;
    float p  = 1.3333558e-3f;
    p = fmaf(p, f, 9.6181290e-3f);
    p = fmaf(p, f, 5.5504109e-2f);
    p = fmaf(p, f, 2.4022651e-1f);
    p = fmaf(p, f, 6.9314718e-1f);
    p = fmaf(p, f, 1.0f);
    return p * __int_as_float((ni + 127) << 23);
}
__device__ __forceinline__ void mma16816(float* d, uint32_t a0, uint32_t a1,
                                         uint32_t a2, uint32_t a3,
                                         uint32_t b0, uint32_t b1) {
    asm volatile(
        "mma.sync.aligned.m16n8k16.row.col.f32.f16.f16.f32 "
        "{%0,%1,%2,%3}, {%4,%5,%6,%7}, {%8,%9}, {%0,%1,%2,%3};"
        : "+f"(d[0]), "+f"(d[1]), "+f"(d[2]), "+f"(d[3])
        : "r"(a0), "r"(a1), "r"(a2), "r"(a3), "r"(b0), "r"(b1));
}
__device__ __forceinline__ void ldsm4(uint32_t& r0, uint32_t& r1,
                                      uint32_t& r2, uint32_t& r3, uint32_t a) {
    asm volatile("ldmatrix.sync.aligned.m8n8.x4.shared.b16 {%0,%1,%2,%3}, [%4];"
                 : "=r"(r0), "=r"(r1), "=r"(r2), "=r"(r3) : "r"(a));
}
__device__ __forceinline__ void ldsm4t(uint32_t& r0, uint32_t& r1,
                                       uint32_t& r2, uint32_t& r3, uint32_t a) {
    asm volatile("ldmatrix.sync.aligned.m8n8.x4.trans.shared.b16 {%0,%1,%2,%3}, [%4];"
                 : "=r"(r0), "=r"(r1), "=r"(r2), "=r"(r3) : "r"(a));
}
__device__ __forceinline__ uint32_t pack_h2(__half a, __half b) {
    __half2 h = __halves2half2(a, b);
    return *(uint32_t*)&h;
}
__device__ __forceinline__ uint32_t smem_u32(const void* p) {
    uint32_t a;
    asm("{ .reg .u64 t; cvta.to.shared.u64 t, %1; cvt.u32.u64 %0, t; }" : "=r"(a) : "l"(p));
    return a;
}
__device__ __forceinline__ void cpasync16(uint32_t dst, const void* src) {
    asm volatile("cp.async.cg.shared.global [%0], [%1], 16;" :: "r"(dst), "l"(src));
}
#define CP_COMMIT() asm volatile("cp.async.commit_group;" ::: "memory")
#define CP_WAIT0()  asm volatile("cp.async.wait_group 0;" ::: "memory")

// ---- prep: fused W-split (blocks 0..575) + t-GEMM (blocks 576..607) ---------
__global__ __launch_bounds__(256) void prep(
    const float* __restrict__ Wf, const float* __restrict__ Ws,
    const float* __restrict__ x, const float* __restrict__ Wt,
    const float* __restrict__ bt)
{
    const int blk = blockIdx.x;
    __shared__ float xs[768];
    if (blk < 384) {
        int i = blk * 256 + threadIdx.x;            // 128*768
        int n = i / 768, k = i - n * 768;
        float v = Wf[(size_t)k * 128 + n] * 256.0f;
        __half hi = __float2half_rn(v);
        g_Bhi[i] = hi;
        g_Blo[i] = __float2half_rn(v - __half2float(hi));
    } else if (blk < 576) {
        int i = (blk - 384) * 256 + threadIdx.x;    // 64*768
        int n = i / 768, k = i - n * 768;
        float v = Ws[(size_t)k * 64 + n] * 256.0f;
        __half hi = __float2half_rn(v);
        g_Bhi[128 * 768 + i] = hi;
        g_Blo[128 * 768 + i] = __float2half_rn(v - __half2float(hi));
    } else {
        const int b = blk - 576;
        const int c = threadIdx.x;
        for (int i = c; i < 768; i += 256) xs[i] = x[(size_t)b * 1025 * 768 + i];
        __syncthreads();
        float acc = bt[c];
        #pragma unroll 8
        for (int d = 0; d < 768; d++) acc = fmaf(xs[d], Wt[(size_t)d * 256 + c], acc);
        g_t[b * 256 + c] = acc;
    }
}

// ---------------------------------------------------------------------------
// gemmA via mma.sync + ldmatrix, double-buffered A and B smem. (frozen)
// ---------------------------------------------------------------------------
#define A_MAT  18432
#define SMA_HI(buf) ((buf) * (2 * A_MAT))
#define SMA_LO_OFF A_MAT
#define B_HI_SZ 27648
#define B_LOS_SZ 9216
#define B_BUF (B_HI_SZ + B_LOS_SZ)
#define SMB_HI(buf) (4 * A_MAT + (buf) * B_BUF)
#define SMB_LOS_OFF B_HI_SZ
#define SM_TOTAL (4 * A_MAT + 2 * B_BUF)      // 147456 B

__global__ __launch_bounds__(512) void gemmA_mma(
    const float* __restrict__ x, const float* __restrict__ bf,
    const float* __restrict__ bs, const float* __restrict__ sharp)
{
    extern __shared__ char sm[];
    const uint32_t smu = smem_u32(sm);
    const int tid = threadIdx.x, wid = tid >> 5, lane = tid & 31;
    const int b = blockIdx.y, nt = blockIdx.x;
    const int wr = wid & 3, wc = wid >> 2;
    const int g = lane >> 2, tig = lane & 3;

    const int rl = lane & 15, kh = lane >> 4;
    const uint32_t aOff   = (uint32_t)((wr * 32 + rl) * 144 + kh * 16);
    const uint32_t bfOff  = (uint32_t)((wc * 32 + rl) * 144 + kh * 16);
    const uint32_t bshOff = (uint32_t)((128 + wc * 16 + rl) * 144 + kh * 16);
    const uint32_t bslOff = (uint32_t)(SMB_LOS_OFF + (wc * 16 + rl) * 144 + kh * 16);

    const float* A = x + (size_t)b * 1025 * 768 + 768 + (size_t)nt * 128 * 768;
    const int am = tid >> 2, akb = (tid & 3) * 16;
    const float* aptr = A + (size_t)am * 768 + akb;
    const uint32_t cvtOff = (uint32_t)(am * 144 + akb * 2);

    float acc[2][6][4];
    float accS2[2][2][4];
    #pragma unroll
    for (int mf = 0; mf < 2; mf++) {
        #pragma unroll
        for (int nf = 0; nf < 6; nf++)
            #pragma unroll
            for (int q = 0; q < 4; q++) acc[mf][nf][q] = 0.0f;
        #pragma unroll
        for (int nf = 0; nf < 2; nf++)
            #pragma unroll
            for (int q = 0; q < 4; q++) accS2[mf][nf][q] = 0.0f;
    }

    float4 aPre[4];
    uint4 h0, h1, l0, l1;

    #define CONVERT_A(WBUF)                                                     \
    do {                                                                        \
        char* dhi = sm + SMA_HI(WBUF) + cvtOff;                                 \
        _Pragma("unroll")                                                       \
        for (int i = 0; i < 4; i++) {                                           \
            float4 v = aPre[i];                                                 \
            __half hx = __float2half_rn(v.x), hy = __float2half_rn(v.y);        \
            __half hz = __float2half_rn(v.z), hw = __float2half_rn(v.w);        \
            __half lx = __float2half_rn(v.x - __half2float(hx));                \
            __half ly = __float2half_rn(v.y - __half2float(hy));                \
            __half lz = __float2half_rn(v.z - __half2float(hz));                \
            __half lw = __float2half_rn(v.w - __half2float(hw));                \
            uint32_t hqa = pack_h2(hx, hy), hqb = pack_h2(hz, hw);              \
            uint32_t lqa = pack_h2(lx, ly), lqb = pack_h2(lz, lw);              \
            if (i == 0) { h0.x = hqa; h0.y = hqb; l0.x = lqa; l0.y = lqb; }     \
            else if (i == 1) { h0.z = hqa; h0.w = hqb; l0.z = lqa; l0.w = lqb; }\
            else if (i == 2) { h1.x = hqa; h1.y = hqb; l1.x = lqa; l1.y = lqb; }\
            else { h1.z = hqa; h1.w = hqb; l1.z = lqa; l1.w = lqb; }            \
        }                                                                       \
        *(uint4*)(dhi) = h0;  *(uint4*)(dhi + 16) = h1;                         \
        *(uint4*)(dhi + SMA_LO_OFF) = l0; *(uint4*)(dhi + SMA_LO_OFF + 16) = l1;\
    } while (0)

    #define FETCH_B(CH, WBUF)                                                   \
    do {                                                                        \
        const int kk0 = (CH) * 64;                                              \
        _Pragma("unroll")                                                       \
        for (int j = 0; j < 3; j++) {                                           \
            int e = tid + j * 512;                                              \
            int n = e >> 3, u = e & 7;                                          \
            cpasync16(smu + SMB_HI(WBUF) + (uint32_t)(n * 144 + u * 16),        \
                      g_Bhi + (size_t)n * 768 + kk0 + u * 8);                   \
        }                                                                       \
        {                                                                       \
            int n = tid >> 3, u = tid & 7;                                      \
            if (n < 64)                                                         \
                cpasync16(smu + SMB_HI(WBUF) + SMB_LOS_OFF +                    \
                          (uint32_t)(n * 144 + u * 16),                         \
                          g_Blo + (size_t)(128 + n) * 768 + kk0 + u * 8);       \
        }                                                                       \
        CP_COMMIT();                                                            \
    } while (0)

    // ---- prologue ----
    #pragma unroll
    for (int i = 0; i < 4; i++) aPre[i] = *(const float4*)(aptr + i * 4);
    FETCH_B(0, 0);
    CONVERT_A(0);
    #pragma unroll
    for (int i = 0; i < 4; i++) aPre[i] = *(const float4*)(aptr + 64 + i * 4);
    CP_WAIT0();
    __syncthreads();

    #pragma unroll 1
    for (int ch = 0; ch < 12; ch++) {
        const int buf = ch & 1;
        if (ch < 11) {
            FETCH_B(ch + 1, buf ^ 1);
            CONVERT_A(buf ^ 1);
            if (ch < 10) {
                const int k2 = (ch + 2) * 64;
                #pragma unroll
                for (int i = 0; i < 4; i++) aPre[i] = *(const float4*)(aptr + k2 + i * 4);
            }
        }

        const uint32_t aHiB = smu + SMA_HI(buf) + aOff;
        const uint32_t aLoB = aHiB + SMA_LO_OFF;
        const uint32_t bHfB = smu + SMB_HI(buf) + bfOff;
        const uint32_t bHsB = smu + SMB_HI(buf) + bshOff;
        const uint32_t bLsB = smu + SMB_HI(buf) + bslOff;
        #pragma unroll
        for (int ks = 0; ks < 4; ks++) {
            const uint32_t ko = ks * 32;
            uint32_t ah[2][4], al[2][4];
            uint32_t bsh0, bsh1, bsh2, bsh3, bsl0, bsl1, bsl2, bsl3;
            uint32_t bfa[4], bfb[4];
            ldsm4(ah[0][0], ah[0][1], ah[0][2], ah[0][3], aHiB + ko);
            ldsm4(ah[1][0], ah[1][1], ah[1][2], ah[1][3], aHiB + 16 * 144 + ko);
            ldsm4(bsh0, bsh1, bsh2, bsh3, bHsB + ko);
            ldsm4(al[0][0], al[0][1], al[0][2], al[0][3], aLoB + ko);
            ldsm4(al[1][0], al[1][1], al[1][2], al[1][3], aLoB + 16 * 144 + ko);
            ldsm4(bsl0, bsl1, bsl2, bsl3, bLsB + ko);
            ldsm4(bfa[0], bfa[1], bfa[2], bfa[3], bHfB + ko);
            ldsm4(bfb[0], bfb[1], bfb[2], bfb[3], bHfB + 16 * 144 + ko);

            mma16816(acc[0][4], ah[0][0], ah[0][1], ah[0][2], ah[0][3], bsh0, bsh2);
            mma16816(acc[0][5], ah[0][0], ah[0][1], ah[0][2], ah[0][3], bsh1, bsh3);
            mma16816(acc[1][4], ah[1][0], ah[1][1], ah[1][2], ah[1][3], bsh0, bsh2);
            mma16816(acc[1][5], ah[1][0], ah[1][1], ah[1][2], ah[1][3], bsh1, bsh3);
            mma16816(acc[0][0], ah[0][0], ah[0][1], ah[0][2], ah[0][3], bfa[0], bfa[2]);
            mma16816(acc[0][1], ah[0][0], ah[0][1], ah[0][2], ah[0][3], bfa[1], bfa[3]);
            mma16816(acc[1][0], ah[1][0], ah[1][1], ah[1][2], ah[1][3], bfa[0], bfa[2]);
            mma16816(acc[1][1], ah[1][0], ah[1][1], ah[1][2], ah[1][3], bfa[1], bfa[3]);
            mma16816(accS2[0][0], ah[0][0], ah[0][1], ah[0][2], ah[0][3], bsl0, bsl2);
            mma16816(accS2[0][1], ah[0][0], ah[0][1], ah[0][2], ah[0][3], bsl1, bsl3);
            mma16816(accS2[1][0], ah[1][0], ah[1][1], ah[1][2], ah[1][3], bsl0, bsl2);
            mma16816(accS2[1][1], ah[1][0], ah[1][1], ah[1][2], ah[1][3], bsl1, bsl3);
            mma16816(acc[0][2], ah[0][0], ah[0][1], ah[0][2], ah[0][3], bfb[0], bfb[2]);
            mma16816(acc[0][3], ah[0][0], ah[0][1], ah[0][2], ah[0][3], bfb[1], bfb[3]);
            mma16816(acc[1][2], ah[1][0], ah[1][1], ah[1][2], ah[1][3], bfb[0], bfb[2]);
            mma16816(acc[1][3], ah[1][0], ah[1][1], ah[1][2], ah[1][3], bfb[1], bfb[3]);
            mma16816(acc[0][4], al[0][0], al[0][1], al[0][2], al[0][3], bsh0, bsh2);
            mma16816(acc[0][5], al[0][0], al[0][1], al[0][2], al[0][3], bsh1, bsh3);
            mma16816(acc[1][4], al[1][0], al[1][1], al[1][2], al[1][3], bsh0, bsh2);
            mma16816(acc[1][5], al[1][0], al[1][1], al[1][2], al[1][3], bsh1, bsh3);
        }
        if (ch < 11) CP_WAIT0();
        __syncthreads();
    }

    // ---------------------------- epilogue ----------------------------------
    const float inv256 = 1.0f / 256.0f;
    const float scl = sharp[0] * 10.0f * LOG2E_F;
    #pragma unroll
    for (int mf = 0; mf < 2; mf++) {
        #pragma unroll
        for (int nf = 0; nf < 4; nf++) {
            int c = wc * 32 + nf * 8 + tig * 2;
            int r0 = nt * 128 + wr * 32 + mf * 16 + g;
            int r1 = r0 + 8;
            float b0 = __ldg(bf + c), b1 = __ldg(bf + c + 1);
            float f00 = fmaf(acc[mf][nf][0], inv256, b0);
            float f01 = fmaf(acc[mf][nf][1], inv256, b1);
            float f10 = fmaf(acc[mf][nf][2], inv256, b0);
            float f11 = fmaf(acc[mf][nf][3], inv256, b1);
            size_t i0 = ((size_t)(b * 1024 + r0)) * 128 + c;
            size_t i1 = ((size_t)(b * 1024 + r1)) * 128 + c;
            *(uint32_t*)(g_fh + i0) = pack_h2(__float2half_rn(f00), __float2half_rn(f01));
            *(uint32_t*)(g_fh + i1) = pack_h2(__float2half_rn(f10), __float2half_rn(f11));
        }
        #pragma unroll
        for (int nf = 4; nf < 6; nf++) {
            int k = wc * 16 + (nf - 4) * 8 + tig * 2;
            int r0 = nt * 128 + wr * 32 + mf * 16 + g;
            int r1 = r0 + 8;
            float b0 = __ldg(bs + k), b1 = __ldg(bs + k + 1);
            float* K0 = g_K + ((size_t)(b * 64 + k)) * 1024;
            float* K1 = g_K + ((size_t)(b * 64 + k + 1)) * 1024;
            float d0 = acc[mf][nf][0] + accS2[mf][nf - 4][0];
            float d1 = acc[mf][nf][1] + accS2[mf][nf - 4][1];
            float d2 = acc[mf][nf][2] + accS2[mf][nf - 4][2];
            float d3 = acc[mf][nf][3] + accS2[mf][nf - 4][3];
            K0[r0] = fmaf(d0, inv256, b0) * scl;
            K1[r0] = fmaf(d1, inv256, b1) * scl;
            K0[r1] = fmaf(d2, inv256, b0) * scl;
            K1[r1] = fmaf(d3, inv256, b1) * scl;
        }
    }
}

// ------ sinkhorn: exp(M')->bf16 K~ + 5 c-updates + 4 r-updates ---------------
__global__ __launch_bounds__(1024) void sinkhorn()
{
    const int b = blockIdx.x;
    const int t = threadIdx.x, w = t >> 5, l = t & 31;
    __shared__ float cs[1024];
    __shared__ float rs[72];
    __shared__ float red[32];
    float* Kb = g_K + ((size_t)b << 16);
    __nv_bfloat16* Khb = g_Kb + ((size_t)b << 16);

    // ---- phase 1: rowmax + exp2 + rowsum; write K~ as bf16 (full exp range) --
    #pragma unroll
    for (int rr = 0; rr < 2; rr++) {
        int k = w + rr * 32;
        const float2* row2 = (const float2*)(Kb + ((size_t)k << 10));
        __nv_bfloat162* o2 = (__nv_bfloat162*)(Khb + ((size_t)k << 10));
        float2 v[16];
        float m = -INFINITY;
        #pragma unroll
        for (int j = 0; j < 16; j++) {
            v[j] = row2[j * 32 + l];
            m = fmaxf(m, fmaxf(v[j].x, v[j].y));
        }
        m = warpMax(m);
        float s = 0.0f;
        #pragma unroll
        for (int j = 0; j < 16; j++) {
            float e0 = exp2_fma(v[j].x - m);
            float e1 = exp2_fma(v[j].y - m);
            s += e0 + e1;
            o2[j * 32 + l] = __floats2bfloat162_rn(e0, e1);
        }
        s = warpSum(s);
        if (l == 0) rs[k] = (1.0f / 65.0f) / s;
    }
    if (t == 0) rs[64] = (1.0f / 65.0f) / 1024.0f;
    __syncthreads();

    // ---- iterations (K~ read as bf16) ----
    #pragma unroll 1
    for (int it = 0; it < 5; it++) {
        // c-update: thread t = column t
        const __nv_bfloat16* col = Khb + t;
        float a0 = rs[64], a1 = 0.f, a2 = 0.f, a3 = 0.f;
        float a4 = 0.f, a5 = 0.f, a6 = 0.f, a7 = 0.f;
        #pragma unroll
        for (int k = 0; k < 64; k += 8) {
            a0 = fmaf(__bfloat162float(col[(size_t)(k + 0) << 10]), rs[k + 0], a0);
            a1 = fmaf(__bfloat162float(col[(size_t)(k + 1) << 10]), rs[k + 1], a1);
            a2 = fmaf(__bfloat162float(col[(size_t)(k + 2) << 10]), rs[k + 2], a2);
            a3 = fmaf(__bfloat162float(col[(size_t)(k + 3) << 10]), rs[k + 3], a3);
            a4 = fmaf(__bfloat162float(col[(size_t)(k + 4) << 10]), rs[k + 4], a4);
            a5 = fmaf(__bfloat162float(col[(size_t)(k + 5) << 10]), rs[k + 5], a5);
            a6 = fmaf(__bfloat162float(col[(size_t)(k + 6) << 10]), rs[k + 6], a6);
            a7 = fmaf(__bfloat162float(col[(size_t)(k + 7) << 10]), rs[k + 7], a7);
        }
        float cv = (1.0f / 1024.0f) /
                   (((a0 + a1) + (a2 + a3)) + ((a4 + a5) + (a6 + a7)));
        cs[t] = cv;
        float sw = warpSum(cv);
        if (l == 0) red[w] = sw;
        __syncthreads();
        if (it < 4) {
            if (t == 0) {
                float s = 0.0f;
                #pragma unroll
                for (int i = 0; i < 32; i++) s += red[i];
                rs[64] = (1.0f / 65.0f) / s;
            }
            // r-update (warp w -> rows w, w+32), bf16x2 loads
            #pragma unroll
            for (int rr = 0; rr < 2; rr++) {
                int k = w + rr * 32;
                const __nv_bfloat162* row2 = (const __nv_bfloat162*)(Khb + ((size_t)k << 10));
                const float2* cs2 = (const float2*)cs;
                float d0 = 0.f, d1 = 0.f, d2 = 0.f, d3 = 0.f;
                float d4 = 0.f, d5 = 0.f, d6 = 0.f, d7 = 0.f;
                #pragma unroll
                for (int j = 0; j < 16; j += 8) {
                    float2 v0 = __bfloat1622float2(row2[(j + 0) * 32 + l]);
                    float2 v1 = __bfloat1622float2(row2[(j + 1) * 32 + l]);
                    float2 v2 = __bfloat1622float2(row2[(j + 2) * 32 + l]);
                    float2 v3 = __bfloat1622float2(row2[(j + 3) * 32 + l]);
                    float2 v4 = __bfloat1622float2(row2[(j + 4) * 32 + l]);
                    float2 v5 = __bfloat1622float2(row2[(j + 5) * 32 + l]);
                    float2 v6 = __bfloat1622float2(row2[(j + 6) * 32 + l]);
                    float2 v7 = __bfloat1622float2(row2[(j + 7) * 32 + l]);
                    float2 c0 = cs2[(j + 0) * 32 + l];
                    float2 c1 = cs2[(j + 1) * 32 + l];
                    float2 c2 = cs2[(j + 2) * 32 + l];
                    float2 c3 = cs2[(j + 3) * 32 + l];
                    float2 c4 = cs2[(j + 4) * 32 + l];
                    float2 c5 = cs2[(j + 5) * 32 + l];
                    float2 c6 = cs2[(j + 6) * 32 + l];
                    float2 c7 = cs2[(j + 7) * 32 + l];
                    d0 = fmaf(v0.x, c0.x, fmaf(v0.y, c0.y, d0));
                    d1 = fmaf(v1.x, c1.x, fmaf(v1.y, c1.y, d1));
                    d2 = fmaf(v2.x, c2.x, fmaf(v2.y, c2.y, d2));
                    d3 = fmaf(v3.x, c3.x, fmaf(v3.y, c3.y, d3));
                    d4 = fmaf(v4.x, c4.x, fmaf(v4.y, c4.y, d4));
                    d5 = fmaf(v5.x, c5.x, fmaf(v5.y, c5.y, d5));
                    d6 = fmaf(v6.x, c6.x, fmaf(v6.y, c6.y, d6));
                    d7 = fmaf(v7.x, c7.x, fmaf(v7.y, c7.y, d7));
                }
                float d = warpSum((((d0 + d1) + (d2 + d3)) + ((d4 + d5) + (d6 + d7))));
                if (l == 0) rs[k] = (1.0f / 65.0f) / d;
            }
            __syncthreads();
        }
    }
    g_c[b * 1024 + t] = cs[t];
    if (t < 65) g_r[b * 65 + t] = rs[t];
}

// ---------------------------------------------------------------------------
// gemmC via mma.sync, single-term fp16 (p_hi x f_hi); K~ read as bf16.
// ---------------------------------------------------------------------------
#define PSH_HI 0
#define FSH_HI 17408
#define SMC_TOTAL (17408 + 34816)   // 52224

__global__ __launch_bounds__(256) void gemmC_mma()
{
    extern __shared__ char sm[];
    const uint32_t smu = smem_u32(sm);
    const int b = blockIdx.y, sp = blockIdx.x;
    const int tid = threadIdx.x, wid = tid >> 5, lane = tid & 31;
    const int wr = wid & 1, wc = wid >> 1;
    const int g = lane >> 2, tig = lane & 3;
    const int rl = lane & 15, kh = lane >> 4;
    const int n0 = sp * 128;

    // ---- fill f tile via cp.async ----
    #pragma unroll
    for (int j = 0; j < 8; j++) {
        int e = tid + j * 256;
        int n = e >> 4, u = e & 15;
        uint32_t doff = (uint32_t)(n * 272 + u * 16);
        size_t src = ((size_t)(b * 1024 + n0 + n)) * 128 + u * 8;
        cpasync16(smu + FSH_HI + doff, g_fh + src);
    }
    CP_COMMIT();

    // ---- build p (scaled x256) into smem fp16 + rowsum ----
    {
        const int k = tid >> 2, nq = (tid & 3) * 32;
        const float rv = __ldg(&g_r[b * 65 + k]) * 256.0f;
        const __nv_bfloat162* Kp2 =
            (const __nv_bfloat162*)(g_Kb + ((size_t)(b * 64 + k)) * 1024 + n0 + nq);
        const float4* Cp = (const float4*)(g_c + b * 1024 + n0 + nq);
        char* ph = sm + PSH_HI + (k * 136 + nq) * 2;
        float psum = 0.0f;
        #pragma unroll
        for (int j = 0; j < 8; j++) {
            float2 k01 = __bfloat1622float2(Kp2[j * 2]);
            float2 k23 = __bfloat1622float2(Kp2[j * 2 + 1]);
            float4 cv = Cp[j];
            float p0 = k01.x * cv.x * rv, p1 = k01.y * cv.y * rv;
            float p2 = k23.x * cv.z * rv, p3 = k23.y * cv.w * rv;
            psum += (p0 + p1) + (p2 + p3);
            *(uint2*)(ph + j * 8) = make_uint2(
                pack_h2(__float2half_rn(p0), __float2half_rn(p1)),
                pack_h2(__float2half_rn(p2), __float2half_rn(p3)));
        }
        psum += __shfl_xor_sync(0xffffffffu, psum, 1);
        psum += __shfl_xor_sync(0xffffffffu, psum, 2);
        if ((tid & 3) == 0)
            g_pspart[(b * 8 + sp) * 64 + k] = psum * (1.0f / 256.0f);
    }
    CP_WAIT0();
    __syncthreads();

    // ---- MMA: M=64 (k), N=128 (c), K=128 (n), single term ----
    float acc[2][4][4];
    #pragma unroll
    for (int mf = 0; mf < 2; mf++)
        #pragma unroll
        for (int nf = 0; nf < 4; nf++)
            #pragma unroll
            for (int q = 0; q < 4; q++) acc[mf][nf][q] = 0.0f;

    const uint32_t pHiB = smu + PSH_HI + (wr * 32 + rl) * 272 + kh * 16;
    const uint32_t fHiB = smu + FSH_HI + rl * 272 + (wc * 32) * 2 + kh * 16;

    #pragma unroll
    for (int s = 0; s < 8; s++) {
        const uint32_t ko = s * 32;
        const uint32_t fo = s * 16 * 272;
        uint32_t ph[2][4];
        uint32_t bh0[4], bh1[4];
        ldsm4(ph[0][0], ph[0][1], ph[0][2], ph[0][3], pHiB + ko);
        ldsm4(ph[1][0], ph[1][1], ph[1][2], ph[1][3], pHiB + 16 * 272 + ko);
        ldsm4t(bh0[0], bh0[1], bh0[2], bh0[3], fHiB + fo);
        ldsm4t(bh1[0], bh1[1], bh1[2], bh1[3], fHiB + fo + 32);

        #pragma unroll
        for (int mf = 0; mf < 2; mf++) {
            mma16816(acc[mf][0], ph[mf][0], ph[mf][1], ph[mf][2], ph[mf][3], bh0[0], bh0[1]);
            mma16816(acc[mf][1], ph[mf][0], ph[mf][1], ph[mf][2], ph[mf][3], bh0[2], bh0[3]);
            mma16816(acc[mf][2], ph[mf][0], ph[mf][1], ph[mf][2], ph[mf][3], bh1[0], bh1[1]);
            mma16816(acc[mf][3], ph[mf][0], ph[mf][1], ph[mf][2], ph[mf][3], bh1[2], bh1[3]);
        }
    }

    // ---- epilogue: vpart = acc / 256 ----
    const float inv256 = 1.0f / 256.0f;
    #pragma unroll
    for (int mf = 0; mf < 2; mf++) {
        #pragma unroll
        for (int nf = 0; nf < 4; nf++) {
            int k0 = wr * 32 + mf * 16 + g;
            int c = wc * 32 + nf * 8 + tig * 2;
            float* base = g_vpart + ((size_t)(b * 8 + sp) * 64) * 128;
            *(float2*)(base + (size_t)k0 * 128 + c) =
                make_float2(acc[mf][nf][0] * inv256, acc[mf][nf][1] * inv256);
            *(float2*)(base + (size_t)(k0 + 8) * 128 + c) =
                make_float2(acc[mf][nf][2] * inv256, acc[mf][nf][3] * inv256);
        }
    }
}

// ----- finalK1: values + partial sumsq (full-chip grid 8x32) -----------------
__global__ __launch_bounds__(256) void finalK1(
    const float* __restrict__ anchors, float* __restrict__ out)
{
    const int b = blockIdx.y, sp = blockIdx.x;
    const int t = threadIdx.x;
    float* orow = out + (size_t)b * 8448;
    float ss = 0.0f;

    #pragma unroll
    for (int j = 0; j < 4; j++) {
        int e = sp * 1024 + j * 256 + t;
        int k = e >> 7, c = e & 127;
        float s2 = 0.0f, sps = 0.0f;
        #pragma unroll
        for (int q = 0; q < 8; q++) {
            s2  += g_vpart[(((size_t)(b * 8 + q) * 64) + k) * 128 + c];
            sps += g_pspart[(b * 8 + q) * 64 + k];
        }
        float val = 2.0f * s2 - sps * anchors[k * 128 + c];
        orow[256 + e] = val;
        ss += val * val;
    }
    if (sp == 0) {
        float tv = g_t[b * 256 + t];
        orow[t] = tv;
        ss += tv * tv;
    }

    __shared__ float red[8];
    float w = warpSum(ss);
    if ((t & 31) == 0) red[t >> 5] = w;
    __syncthreads();
    if (t == 0) {
        float s = 0.0f;
        #pragma unroll
        for (int i = 0; i < 8; i++) s += red[i];
        g_ssp[b * 8 + sp] = s;
    }
}

// ----- finalK2: reduce sumsq partials + normalize ----------------------------
__global__ __launch_bounds__(1024) void finalK2(float* __restrict__ out)
{
    const int b = blockIdx.x, t = threadIdx.x;
    __shared__ float s_inv;
    if (t == 0) {
        float s = 0.0f;
        #pragma unroll
        for (int i = 0; i < 8; i++) s += g_ssp[b * 8 + i];
        s_inv = 1.0f / fmaxf(sqrtf(s), 1e-12f);
    }
    __syncthreads();
    const float inv = s_inv;
    float* orow = out + (size_t)b * 8448;
    for (int idx = t; idx < 8448; idx += 1024) orow[idx] *= inv;
}

// ---------------------------------------------------------------------------
extern "C" void kernel_launch(void* const* d_in, const int* in_sizes, int n_in,
                              void* d_out, int out_size)
{
    const float* x       = (const float*)d_in[0];
    const float* Wf      = (const float*)d_in[1];
    const float* bf      = (const float*)d_in[2];
    const float* Ws      = (const float*)d_in[3];
    const float* bs      = (const float*)d_in[4];
    const float* Wt      = (const float*)d_in[5];
    const float* bt      = (const float*)d_in[6];
    const float* anchors = (const float*)d_in[7];
    // d_in[8] = dust_bin: constant row shift, cancels in the transport plan.
    const float* sharp   = (const float*)d_in[9];
    float* out = (float*)d_out;

    static int smem_set = 0;
    if (!smem_set) {
        cudaFuncSetAttribute(gemmA_mma, cudaFuncAttributeMaxDynamicSharedMemorySize, SM_TOTAL);
        cudaFuncSetAttribute(gemmC_mma, cudaFuncAttributeMaxDynamicSharedMemorySize, SMC_TOTAL);
        smem_set = 1;
    }

    prep<<<608, 256>>>(Wf, Ws, x, Wt, bt);
    gemmA_mma<<<dim3(8, 32), 512, SM_TOTAL>>>(x, bf, bs, sharp);
    sinkhorn<<<32, 1024>>>();
    gemmC_mma<<<dim3(8, 32), 256, SMC_TOTAL>>>();
    finalK1<<<dim3(8, 32), 256>>>(anchors, out);
    finalK2<<<32, 1024>>>(out);
}

// round 15
// speedup vs baseline: 1.0617x; 1.0037x over previous
#include <cuda_runtime.h>
#include <cuda_fp16.h>
#include <cuda_bf16.h>
#include <math.h>
#include <stdint.h>

#define LOG2E_F 1.4426950408889634f

// ---------------- scratch (static device globals; no allocs) ----------------
__device__ float  g_K[32 * 64 * 1024];        // M' (fp32, pre-exp)        8 MB
__device__ __nv_bfloat16 g_Kb[32 * 64 * 1024];// K~ = exp2(M'-max), bf16   4 MB
__device__ float  g_r[32 * 65];               // Sinkhorn row scalings
__device__ float  g_c[32 * 1024];             // Sinkhorn col scalings
__device__ float  g_vpart[32 * 8 * 64 * 128]; // split-K partials of p@f
__device__ float  g_pspart[32 * 8 * 64];      // split-K partials of rowsum(p)
__device__ float  g_ssp[32 * 8];              // per-(b,sp) sumsq partials
__device__ float  g_t[32 * 256];              // t = x0 @ Wt + bt
__device__ __half g_Bhi[192 * 768];           // (W^T * 256) hi, [n][k]
__device__ __half g_Blo[192 * 768];           // (W^T * 256) lo
__device__ __half g_fh[32 * 1024 * 128];      // f (half)                 8 MB

// ------------------------------- helpers -------------------------------------
__device__ __forceinline__ float warpSum(float v) {
    #pragma unroll
    for (int o = 16; o > 0; o >>= 1) v += __shfl_xor_sync(0xffffffffu, v, o);
    return v;
}
__device__ __forceinline__ float warpMax(float v) {
    #pragma unroll
    for (int o = 16; o > 0; o >>= 1) v = fmaxf(v, __shfl_xor_sync(0xffffffffu, v, o));
    return v;
}
// exp2 on the FMA pipe (x <= 0 here). deg-5 Taylor, rel err ~2e-6.
__device__ __forceinline__ float exp2_fma(float x) {
    x = fmaxf(x, -125.0f);
    int   ni = __float2int_rn(x);
    float f  = x - (float)ni;
    float p  = 1.3333558e-3f;
    p = fmaf(p, f, 9.6181290e-3f);
    p = fmaf(p, f, 5.5504109e-2f);
    p = fmaf(p, f, 2.4022651e-1f);
    p = fmaf(p, f, 6.9314718e-1f);
    p = fmaf(p, f, 1.0f);
    return p * __int_as_float((ni + 127) << 23);
}
__device__ __forceinline__ void mma16816(float* d, uint32_t a0, uint32_t a1,
                                         uint32_t a2, uint32_t a3,
                                         uint32_t b0, uint32_t b1) {
    asm volatile(
        "mma.sync.aligned.m16n8k16.row.col.f32.f16.f16.f32 "
        "{%0,%1,%2,%3}, {%4,%5,%6,%7}, {%8,%9}, {%0,%1,%2,%3};"
        : "+f"(d[0]), "+f"(d[1]), "+f"(d[2]), "+f"(d[3])
        : "r"(a0), "r"(a1), "r"(a2), "r"(a3), "r"(b0), "r"(b1));
}
__device__ __forceinline__ void ldsm4(uint32_t& r0, uint32_t& r1,
                                      uint32_t& r2, uint32_t& r3, uint32_t a) {
    asm volatile("ldmatrix.sync.aligned.m8n8.x4.shared.b16 {%0,%1,%2,%3}, [%4];"
                 : "=r"(r0), "=r"(r1), "=r"(r2), "=r"(r3) : "r"(a));
}
__device__ __forceinline__ void ldsm4t(uint32_t& r0, uint32_t& r1,
                                       uint32_t& r2, uint32_t& r3, uint32_t a) {
    asm volatile("ldmatrix.sync.aligned.m8n8.x4.trans.shared.b16 {%0,%1,%2,%3}, [%4];"
                 : "=r"(r0), "=r"(r1), "=r"(r2), "=r"(r3) : "r"(a));
}
__device__ __forceinline__ uint32_t pack_h2(__half a, __half b) {
    __half2 h = __halves2half2(a, b);
    return *(uint32_t*)&h;
}
__device__ __forceinline__ uint32_t smem_u32(const void* p) {
    uint32_t a;
    asm("{ .reg .u64 t; cvta.to.shared.u64 t, %1; cvt.u32.u64 %0, t; }" : "=r"(a) : "l"(p));
    return a;
}
__device__ __forceinline__ void cpasync16(uint32_t dst, const void* src) {
    asm volatile("cp.async.cg.shared.global [%0], [%1], 16;" :: "r"(dst), "l"(src));
}
#define CP_COMMIT() asm volatile("cp.async.commit_group;" ::: "memory")
#define CP_WAIT0()  asm volatile("cp.async.wait_group 0;" ::: "memory")

// ---- prep: fused W-split (blocks 0..575) + t-GEMM (blocks 576..607) ---------
__global__ __launch_bounds__(256) void prep(
    const float* __restrict__ Wf, const float* __restrict__ Ws,
    const float* __restrict__ x, const float* __restrict__ Wt,
    const float* __restrict__ bt)
{
    const int blk = blockIdx.x;
    __shared__ float xs[768];
    if (blk < 384) {
        int i = blk * 256 + threadIdx.x;            // 128*768
        int n = i / 768, k = i - n * 768;
        float v = Wf[(size_t)k * 128 + n] * 256.0f;
        __half hi = __float2half_rn(v);
        g_Bhi[i] = hi;
        g_Blo[i] = __float2half_rn(v - __half2float(hi));
    } else if (blk < 576) {
        int i = (blk - 384) * 256 + threadIdx.x;    // 64*768
        int n = i / 768, k = i - n * 768;
        float v = Ws[(size_t)k * 64 + n] * 256.0f;
        __half hi = __float2half_rn(v);
        g_Bhi[128 * 768 + i] = hi;
        g_Blo[128 * 768 + i] = __float2half_rn(v - __half2float(hi));
    } else {
        const int b = blk - 576;
        const int c = threadIdx.x;
        for (int i = c; i < 768; i += 256) xs[i] = x[(size_t)b * 1025 * 768 + i];
        __syncthreads();
        float acc = bt[c];
        #pragma unroll 8
        for (int d = 0; d < 768; d++) acc = fmaf(xs[d], Wt[(size_t)d * 256 + c], acc);
        g_t[b * 256 + c] = acc;
    }
}

// ---------------------------------------------------------------------------
// gemmA via mma.sync + ldmatrix, double-buffered A and B smem. (frozen)
// ---------------------------------------------------------------------------
#define A_MAT  18432
#define SMA_HI(buf) ((buf) * (2 * A_MAT))
#define SMA_LO_OFF A_MAT
#define B_HI_SZ 27648
#define B_LOS_SZ 9216
#define B_BUF (B_HI_SZ + B_LOS_SZ)
#define SMB_HI(buf) (4 * A_MAT + (buf) * B_BUF)
#define SMB_LOS_OFF B_HI_SZ
#define SM_TOTAL (4 * A_MAT + 2 * B_BUF)      // 147456 B

__global__ __launch_bounds__(512) void gemmA_mma(
    const float* __restrict__ x, const float* __restrict__ bf,
    const float* __restrict__ bs, const float* __restrict__ sharp)
{
    extern __shared__ char sm[];
    const uint32_t smu = smem_u32(sm);
    const int tid = threadIdx.x, wid = tid >> 5, lane = tid & 31;
    const int b = blockIdx.y, nt = blockIdx.x;
    const int wr = wid & 3, wc = wid >> 2;
    const int g = lane >> 2, tig = lane & 3;

    const int rl = lane & 15, kh = lane >> 4;
    const uint32_t aOff   = (uint32_t)((wr * 32 + rl) * 144 + kh * 16);
    const uint32_t bfOff  = (uint32_t)((wc * 32 + rl) * 144 + kh * 16);
    const uint32_t bshOff = (uint32_t)((128 + wc * 16 + rl) * 144 + kh * 16);
    const uint32_t bslOff = (uint32_t)(SMB_LOS_OFF + (wc * 16 + rl) * 144 + kh * 16);

    const float* A = x + (size_t)b * 1025 * 768 + 768 + (size_t)nt * 128 * 768;
    const int am = tid >> 2, akb = (tid & 3) * 16;
    const float* aptr = A + (size_t)am * 768 + akb;
    const uint32_t cvtOff = (uint32_t)(am * 144 + akb * 2);

    float acc[2][6][4];
    float accS2[2][2][4];
    #pragma unroll
    for (int mf = 0; mf < 2; mf++) {
        #pragma unroll
        for (int nf = 0; nf < 6; nf++)
            #pragma unroll
            for (int q = 0; q < 4; q++) acc[mf][nf][q] = 0.0f;
        #pragma unroll
        for (int nf = 0; nf < 2; nf++)
            #pragma unroll
            for (int q = 0; q < 4; q++) accS2[mf][nf][q] = 0.0f;
    }

    float4 aPre[4];
    uint4 h0, h1, l0, l1;

    #define CONVERT_A(WBUF)                                                     \
    do {                                                                        \
        char* dhi = sm + SMA_HI(WBUF) + cvtOff;                                 \
        _Pragma("unroll")                                                       \
        for (int i = 0; i < 4; i++) {                                           \
            float4 v = aPre[i];                                                 \
            __half hx = __float2half_rn(v.x), hy = __float2half_rn(v.y);        \
            __half hz = __float2half_rn(v.z), hw = __float2half_rn(v.w);        \
            __half lx = __float2half_rn(v.x - __half2float(hx));                \
            __half ly = __float2half_rn(v.y - __half2float(hy));                \
            __half lz = __float2half_rn(v.z - __half2float(hz));                \
            __half lw = __float2half_rn(v.w - __half2float(hw));                \
            uint32_t hqa = pack_h2(hx, hy), hqb = pack_h2(hz, hw);              \
            uint32_t lqa = pack_h2(lx, ly), lqb = pack_h2(lz, lw);              \
            if (i == 0) { h0.x = hqa; h0.y = hqb; l0.x = lqa; l0.y = lqb; }     \
            else if (i == 1) { h0.z = hqa; h0.w = hqb; l0.z = lqa; l0.w = lqb; }\
            else if (i == 2) { h1.x = hqa; h1.y = hqb; l1.x = lqa; l1.y = lqb; }\
            else { h1.z = hqa; h1.w = hqb; l1.z = lqa; l1.w = lqb; }            \
        }                                                                       \
        *(uint4*)(dhi) = h0;  *(uint4*)(dhi + 16) = h1;                         \
        *(uint4*)(dhi + SMA_LO_OFF) = l0; *(uint4*)(dhi + SMA_LO_OFF + 16) = l1;\
    } while (0)

    #define FETCH_B(CH, WBUF)                                                   \
    do {                                                                        \
        const int kk0 = (CH) * 64;                                              \
        _Pragma("unroll")                                                       \
        for (int j = 0; j < 3; j++) {                                           \
            int e = tid + j * 512;                                              \
            int n = e >> 3, u = e & 7;                                          \
            cpasync16(smu + SMB_HI(WBUF) + (uint32_t)(n * 144 + u * 16),        \
                      g_Bhi + (size_t)n * 768 + kk0 + u * 8);                   \
        }                                                                       \
        {                                                                       \
            int n = tid >> 3, u = tid & 7;                                      \
            if (n < 64)                                                         \
                cpasync16(smu + SMB_HI(WBUF) + SMB_LOS_OFF +                    \
                          (uint32_t)(n * 144 + u * 16),                         \
                          g_Blo + (size_t)(128 + n) * 768 + kk0 + u * 8);       \
        }                                                                       \
        CP_COMMIT();                                                            \
    } while (0)

    // ---- prologue ----
    #pragma unroll
    for (int i = 0; i < 4; i++) aPre[i] = *(const float4*)(aptr + i * 4);
    FETCH_B(0, 0);
    CONVERT_A(0);
    #pragma unroll
    for (int i = 0; i < 4; i++) aPre[i] = *(const float4*)(aptr + 64 + i * 4);
    CP_WAIT0();
    __syncthreads();

    #pragma unroll 1
    for (int ch = 0; ch < 12; ch++) {
        const int buf = ch & 1;
        if (ch < 11) {
            FETCH_B(ch + 1, buf ^ 1);
            CONVERT_A(buf ^ 1);
            if (ch < 10) {
                const int k2 = (ch + 2) * 64;
                #pragma unroll
                for (int i = 0; i < 4; i++) aPre[i] = *(const float4*)(aptr + k2 + i * 4);
            }
        }

        const uint32_t aHiB = smu + SMA_HI(buf) + aOff;
        const uint32_t aLoB = aHiB + SMA_LO_OFF;
        const uint32_t bHfB = smu + SMB_HI(buf) + bfOff;
        const uint32_t bHsB = smu + SMB_HI(buf) + bshOff;
        const uint32_t bLsB = smu + SMB_HI(buf) + bslOff;
        #pragma unroll
        for (int ks = 0; ks < 4; ks++) {
            const uint32_t ko = ks * 32;
            uint32_t ah[2][4], al[2][4];
            uint32_t bsh0, bsh1, bsh2, bsh3, bsl0, bsl1, bsl2, bsl3;
            uint32_t bfa[4], bfb[4];
            ldsm4(ah[0][0], ah[0][1], ah[0][2], ah[0][3], aHiB + ko);
            ldsm4(ah[1][0], ah[1][1], ah[1][2], ah[1][3], aHiB + 16 * 144 + ko);
            ldsm4(bsh0, bsh1, bsh2, bsh3, bHsB + ko);
            ldsm4(al[0][0], al[0][1], al[0][2], al[0][3], aLoB + ko);
            ldsm4(al[1][0], al[1][1], al[1][2], al[1][3], aLoB + 16 * 144 + ko);
            ldsm4(bsl0, bsl1, bsl2, bsl3, bLsB + ko);
            ldsm4(bfa[0], bfa[1], bfa[2], bfa[3], bHfB + ko);
            ldsm4(bfb[0], bfb[1], bfb[2], bfb[3], bHfB + 16 * 144 + ko);

            mma16816(acc[0][4], ah[0][0], ah[0][1], ah[0][2], ah[0][3], bsh0, bsh2);
            mma16816(acc[0][5], ah[0][0], ah[0][1], ah[0][2], ah[0][3], bsh1, bsh3);
            mma16816(acc[1][4], ah[1][0], ah[1][1], ah[1][2], ah[1][3], bsh0, bsh2);
            mma16816(acc[1][5], ah[1][0], ah[1][1], ah[1][2], ah[1][3], bsh1, bsh3);
            mma16816(acc[0][0], ah[0][0], ah[0][1], ah[0][2], ah[0][3], bfa[0], bfa[2]);
            mma16816(acc[0][1], ah[0][0], ah[0][1], ah[0][2], ah[0][3], bfa[1], bfa[3]);
            mma16816(acc[1][0], ah[1][0], ah[1][1], ah[1][2], ah[1][3], bfa[0], bfa[2]);
            mma16816(acc[1][1], ah[1][0], ah[1][1], ah[1][2], ah[1][3], bfa[1], bfa[3]);
            mma16816(accS2[0][0], ah[0][0], ah[0][1], ah[0][2], ah[0][3], bsl0, bsl2);
            mma16816(accS2[0][1], ah[0][0], ah[0][1], ah[0][2], ah[0][3], bsl1, bsl3);
            mma16816(accS2[1][0], ah[1][0], ah[1][1], ah[1][2], ah[1][3], bsl0, bsl2);
            mma16816(accS2[1][1], ah[1][0], ah[1][1], ah[1][2], ah[1][3], bsl1, bsl3);
            mma16816(acc[0][2], ah[0][0], ah[0][1], ah[0][2], ah[0][3], bfb[0], bfb[2]);
            mma16816(acc[0][3], ah[0][0], ah[0][1], ah[0][2], ah[0][3], bfb[1], bfb[3]);
            mma16816(acc[1][2], ah[1][0], ah[1][1], ah[1][2], ah[1][3], bfb[0], bfb[2]);
            mma16816(acc[1][3], ah[1][0], ah[1][1], ah[1][2], ah[1][3], bfb[1], bfb[3]);
            mma16816(acc[0][4], al[0][0], al[0][1], al[0][2], al[0][3], bsh0, bsh2);
            mma16816(acc[0][5], al[0][0], al[0][1], al[0][2], al[0][3], bsh1, bsh3);
            mma16816(acc[1][4], al[1][0], al[1][1], al[1][2], al[1][3], bsh0, bsh2);
            mma16816(acc[1][5], al[1][0], al[1][1], al[1][2], al[1][3], bsh1, bsh3);
        }
        if (ch < 11) CP_WAIT0();
        __syncthreads();
    }

    // ---------------------------- epilogue ----------------------------------
    const float inv256 = 1.0f / 256.0f;
    const float scl = sharp[0] * 10.0f * LOG2E_F;
    #pragma unroll
    for (int mf = 0; mf < 2; mf++) {
        #pragma unroll
        for (int nf = 0; nf < 4; nf++) {
            int c = wc * 32 + nf * 8 + tig * 2;
            int r0 = nt * 128 + wr * 32 + mf * 16 + g;
            int r1 = r0 + 8;
            float b0 = __ldg(bf + c), b1 = __ldg(bf + c + 1);
            float f00 = fmaf(acc[mf][nf][0], inv256, b0);
            float f01 = fmaf(acc[mf][nf][1], inv256, b1);
            float f10 = fmaf(acc[mf][nf][2], inv256, b0);
            float f11 = fmaf(acc[mf][nf][3], inv256, b1);
            size_t i0 = ((size_t)(b * 1024 + r0)) * 128 + c;
            size_t i1 = ((size_t)(b * 1024 + r1)) * 128 + c;
            *(uint32_t*)(g_fh + i0) = pack_h2(__float2half_rn(f00), __float2half_rn(f01));
            *(uint32_t*)(g_fh + i1) = pack_h2(__float2half_rn(f10), __float2half_rn(f11));
        }
        #pragma unroll
        for (int nf = 4; nf < 6; nf++) {
            int k = wc * 16 + (nf - 4) * 8 + tig * 2;
            int r0 = nt * 128 + wr * 32 + mf * 16 + g;
            int r1 = r0 + 8;
            float b0 = __ldg(bs + k), b1 = __ldg(bs + k + 1);
            float* K0 = g_K + ((size_t)(b * 64 + k)) * 1024;
            float* K1 = g_K + ((size_t)(b * 64 + k + 1)) * 1024;
            float d0 = acc[mf][nf][0] + accS2[mf][nf - 4][0];
            float d1 = acc[mf][nf][1] + accS2[mf][nf - 4][1];
            float d2 = acc[mf][nf][2] + accS2[mf][nf - 4][2];
            float d3 = acc[mf][nf][3] + accS2[mf][nf - 4][3];
            K0[r0] = fmaf(d0, inv256, b0) * scl;
            K1[r0] = fmaf(d1, inv256, b1) * scl;
            K0[r1] = fmaf(d2, inv256, b0) * scl;
            K1[r1] = fmaf(d3, inv256, b1) * scl;
        }
    }
}

// ------ sinkhorn: K~ resident in SMEM (128 KB) for all 9 iteration passes ----
// smem: K~ [64][1024] bf16 (131072 B) | cs[1024] f32 | rs[72] | red[32]
#define SK_KS   0
#define SK_CS   131072
#define SK_RS   (131072 + 4096)
#define SK_RED  (SK_RS + 288)
#define SK_TOTAL (SK_RED + 128)

__global__ __launch_bounds__(1024) void sinkhorn()
{
    extern __shared__ char ssm[];
    __nv_bfloat16* Ks = (__nv_bfloat16*)(ssm + SK_KS);
    float* cs  = (float*)(ssm + SK_CS);
    float* rs  = (float*)(ssm + SK_RS);
    float* red = (float*)(ssm + SK_RED);

    const int b = blockIdx.x;
    const int t = threadIdx.x, w = t >> 5, l = t & 31;
    const float* Kb = g_K + ((size_t)b << 16);
    __nv_bfloat16* Khg = g_Kb + ((size_t)b << 16);

    // ---- phase 1: rowmax + exp2 + rowsum; K~ -> smem AND global(bf16) ----
    #pragma unroll
    for (int rr = 0; rr < 2; rr++) {
        int k = w + rr * 32;
        const float2* row2 = (const float2*)(Kb + ((size_t)k << 10));
        __nv_bfloat162* oS = (__nv_bfloat162*)(Ks + ((size_t)k << 10));
        __nv_bfloat162* oG = (__nv_bfloat162*)(Khg + ((size_t)k << 10));
        float2 v[16];
        float m = -INFINITY;
        #pragma unroll
        for (int j = 0; j < 16; j++) {
            v[j] = row2[j * 32 + l];
            m = fmaxf(m, fmaxf(v[j].x, v[j].y));
        }
        m = warpMax(m);
        float s = 0.0f;
        #pragma unroll
        for (int j = 0; j < 16; j++) {
            float e0 = exp2_fma(v[j].x - m);
            float e1 = exp2_fma(v[j].y - m);
            s += e0 + e1;
            __nv_bfloat162 e2 = __floats2bfloat162_rn(e0, e1);
            oS[j * 32 + l] = e2;
            oG[j * 32 + l] = e2;
        }
        s = warpSum(s);
        if (l == 0) rs[k] = (1.0f / 65.0f) / s;
    }
    if (t == 0) rs[64] = (1.0f / 65.0f) / 1024.0f;
    __syncthreads();

    // ---- iterations, fully smem-resident ----
    #pragma unroll 1
    for (int it = 0; it < 5; it++) {
        // c-update: thread t = column t
        const __nv_bfloat16* col = Ks + t;
        float a0 = rs[64], a1 = 0.f, a2 = 0.f, a3 = 0.f;
        float a4 = 0.f, a5 = 0.f, a6 = 0.f, a7 = 0.f;
        #pragma unroll
        for (int k = 0; k < 64; k += 8) {
            a0 = fmaf(__bfloat162float(col[(size_t)(k + 0) << 10]), rs[k + 0], a0);
            a1 = fmaf(__bfloat162float(col[(size_t)(k + 1) << 10]), rs[k + 1], a1);
            a2 = fmaf(__bfloat162float(col[(size_t)(k + 2) << 10]), rs[k + 2], a2);
            a3 = fmaf(__bfloat162float(col[(size_t)(k + 3) << 10]), rs[k + 3], a3);
            a4 = fmaf(__bfloat162float(col[(size_t)(k + 4) << 10]), rs[k + 4], a4);
            a5 = fmaf(__bfloat162float(col[(size_t)(k + 5) << 10]), rs[k + 5], a5);
            a6 = fmaf(__bfloat162float(col[(size_t)(k + 6) << 10]), rs[k + 6], a6);
            a7 = fmaf(__bfloat162float(col[(size_t)(k + 7) << 10]), rs[k + 7], a7);
        }
        float cv = (1.0f / 1024.0f) /
                   (((a0 + a1) + (a2 + a3)) + ((a4 + a5) + (a6 + a7)));
        cs[t] = cv;
        float sw = warpSum(cv);
        if (l == 0) red[w] = sw;
        __syncthreads();
        if (it < 4) {
            if (t == 0) {
                float s = 0.0f;
                #pragma unroll
                for (int i = 0; i < 32; i++) s += red[i];
                rs[64] = (1.0f / 65.0f) / s;
            }
            // r-update (warp w -> rows w, w+32)
            #pragma unroll
            for (int rr = 0; rr < 2; rr++) {
                int k = w + rr * 32;
                const __nv_bfloat162* row2 = (const __nv_bfloat162*)(Ks + ((size_t)k << 10));
                const float2* cs2 = (const float2*)cs;
                float d0 = 0.f, d1 = 0.f, d2 = 0.f, d3 = 0.f;
                float d4 = 0.f, d5 = 0.f, d6 = 0.f, d7 = 0.f;
                #pragma unroll
                for (int j = 0; j < 16; j += 8) {
                    float2 v0 = __bfloat1622float2(row2[(j + 0) * 32 + l]);
                    float2 v1 = __bfloat1622float2(row2[(j + 1) * 32 + l]);
                    float2 v2 = __bfloat1622float2(row2[(j + 2) * 32 + l]);
                    float2 v3 = __bfloat1622float2(row2[(j + 3) * 32 + l]);
                    float2 v4 = __bfloat1622float2(row2[(j + 4) * 32 + l]);
                    float2 v5 = __bfloat1622float2(row2[(j + 5) * 32 + l]);
                    float2 v6 = __bfloat1622float2(row2[(j + 6) * 32 + l]);
                    float2 v7 = __bfloat1622float2(row2[(j + 7) * 32 + l]);
                    float2 c0 = cs2[(j + 0) * 32 + l];
                    float2 c1 = cs2[(j + 1) * 32 + l];
                    float2 c2 = cs2[(j + 2) * 32 + l];
                    float2 c3 = cs2[(j + 3) * 32 + l];
                    float2 c4 = cs2[(j + 4) * 32 + l];
                    float2 c5 = cs2[(j + 5) * 32 + l];
                    float2 c6 = cs2[(j + 6) * 32 + l];
                    float2 c7 = cs2[(j + 7) * 32 + l];
                    d0 = fmaf(v0.x, c0.x, fmaf(v0.y, c0.y, d0));
                    d1 = fmaf(v1.x, c1.x, fmaf(v1.y, c1.y, d1));
                    d2 = fmaf(v2.x, c2.x, fmaf(v2.y, c2.y, d2));
                    d3 = fmaf(v3.x, c3.x, fmaf(v3.y, c3.y, d3));
                    d4 = fmaf(v4.x, c4.x, fmaf(v4.y, c4.y, d4));
                    d5 = fmaf(v5.x, c5.x, fmaf(v5.y, c5.y, d5));
                    d6 = fmaf(v6.x, c6.x, fmaf(v6.y, c6.y, d6));
                    d7 = fmaf(v7.x, c7.x, fmaf(v7.y, c7.y, d7));
                }
                float d = warpSum((((d0 + d1) + (d2 + d3)) + ((d4 + d5) + (d6 + d7))));
                if (l == 0) rs[k] = (1.0f / 65.0f) / d;
            }
            __syncthreads();
        }
    }
    g_c[b * 1024 + t] = cs[t];
    if (t < 65) g_r[b * 65 + t] = rs[t];
}

// ---------------------------------------------------------------------------
// gemmC via mma.sync, single-term fp16 (p_hi x f_hi); K~ read as bf16.
// ---------------------------------------------------------------------------
#define PSH_HI 0
#define FSH_HI 17408
#define SMC_TOTAL (17408 + 34816)   // 52224

__global__ __launch_bounds__(256) void gemmC_mma()
{
    extern __shared__ char sm[];
    const uint32_t smu = smem_u32(sm);
    const int b = blockIdx.y, sp = blockIdx.x;
    const int tid = threadIdx.x, wid = tid >> 5, lane = tid & 31;
    const int wr = wid & 1, wc = wid >> 1;
    const int g = lane >> 2, tig = lane & 3;
    const int rl = lane & 15, kh = lane >> 4;
    const int n0 = sp * 128;

    // ---- fill f tile via cp.async ----
    #pragma unroll
    for (int j = 0; j < 8; j++) {
        int e = tid + j * 256;
        int n = e >> 4, u = e & 15;
        uint32_t doff = (uint32_t)(n * 272 + u * 16);
        size_t src = ((size_t)(b * 1024 + n0 + n)) * 128 + u * 8;
        cpasync16(smu + FSH_HI + doff, g_fh + src);
    }
    CP_COMMIT();

    // ---- build p (scaled x256) into smem fp16 + rowsum ----
    {
        const int k = tid >> 2, nq = (tid & 3) * 32;
        const float rv = __ldg(&g_r[b * 65 + k]) * 256.0f;
        const __nv_bfloat162* Kp2 =
            (const __nv_bfloat162*)(g_Kb + ((size_t)(b * 64 + k)) * 1024 + n0 + nq);
        const float4* Cp = (const float4*)(g_c + b * 1024 + n0 + nq);
        char* ph = sm + PSH_HI + (k * 136 + nq) * 2;
        float psum = 0.0f;
        #pragma unroll
        for (int j = 0; j < 8; j++) {
            float2 k01 = __bfloat1622float2(Kp2[j * 2]);
            float2 k23 = __bfloat1622float2(Kp2[j * 2 + 1]);
            float4 cv = Cp[j];
            float p0 = k01.x * cv.x * rv, p1 = k01.y * cv.y * rv;
            float p2 = k23.x * cv.z * rv, p3 = k23.y * cv.w * rv;
            psum += (p0 + p1) + (p2 + p3);
            *(uint2*)(ph + j * 8) = make_uint2(
                pack_h2(__float2half_rn(p0), __float2half_rn(p1)),
                pack_h2(__float2half_rn(p2), __float2half_rn(p3)));
        }
        psum += __shfl_xor_sync(0xffffffffu, psum, 1);
        psum += __shfl_xor_sync(0xffffffffu, psum, 2);
        if ((tid & 3) == 0)
            g_pspart[(b * 8 + sp) * 64 + k] = psum * (1.0f / 256.0f);
    }
    CP_WAIT0();
    __syncthreads();

    // ---- MMA: M=64 (k), N=128 (c), K=128 (n), single term ----
    float acc[2][4][4];
    #pragma unroll
    for (int mf = 0; mf < 2; mf++)
        #pragma unroll
        for (int nf = 0; nf < 4; nf++)
            #pragma unroll
            for (int q = 0; q < 4; q++) acc[mf][nf][q] = 0.0f;

    const uint32_t pHiB = smu + PSH_HI + (wr * 32 + rl) * 272 + kh * 16;
    const uint32_t fHiB = smu + FSH_HI + rl * 272 + (wc * 32) * 2 + kh * 16;

    #pragma unroll
    for (int s = 0; s < 8; s++) {
        const uint32_t ko = s * 32;
        const uint32_t fo = s * 16 * 272;
        uint32_t ph[2][4];
        uint32_t bh0[4], bh1[4];
        ldsm4(ph[0][0], ph[0][1], ph[0][2], ph[0][3], pHiB + ko);
        ldsm4(ph[1][0], ph[1][1], ph[1][2], ph[1][3], pHiB + 16 * 272 + ko);
        ldsm4t(bh0[0], bh0[1], bh0[2], bh0[3], fHiB + fo);
        ldsm4t(bh1[0], bh1[1], bh1[2], bh1[3], fHiB + fo + 32);

        #pragma unroll
        for (int mf = 0; mf < 2; mf++) {
            mma16816(acc[mf][0], ph[mf][0], ph[mf][1], ph[mf][2], ph[mf][3], bh0[0], bh0[1]);
            mma16816(acc[mf][1], ph[mf][0], ph[mf][1], ph[mf][2], ph[mf][3], bh0[2], bh0[3]);
            mma16816(acc[mf][2], ph[mf][0], ph[mf][1], ph[mf][2], ph[mf][3], bh1[0], bh1[1]);
            mma16816(acc[mf][3], ph[mf][0], ph[mf][1], ph[mf][2], ph[mf][3], bh1[2], bh1[3]);
        }
    }

    // ---- epilogue: vpart = acc / 256 ----
    const float inv256 = 1.0f / 256.0f;
    #pragma unroll
    for (int mf = 0; mf < 2; mf++) {
        #pragma unroll
        for (int nf = 0; nf < 4; nf++) {
            int k0 = wr * 32 + mf * 16 + g;
            int c = wc * 32 + nf * 8 + tig * 2;
            float* base = g_vpart + ((size_t)(b * 8 + sp) * 64) * 128;
            *(float2*)(base + (size_t)k0 * 128 + c) =
                make_float2(acc[mf][nf][0] * inv256, acc[mf][nf][1] * inv256);
            *(float2*)(base + (size_t)(k0 + 8) * 128 + c) =
                make_float2(acc[mf][nf][2] * inv256, acc[mf][nf][3] * inv256);
        }
    }
}

// ----- finalK1: values + partial sumsq (full-chip grid 8x32) -----------------
__global__ __launch_bounds__(256) void finalK1(
    const float* __restrict__ anchors, float* __restrict__ out)
{
    const int b = blockIdx.y, sp = blockIdx.x;
    const int t = threadIdx.x;
    float* orow = out + (size_t)b * 8448;
    float ss = 0.0f;

    #pragma unroll
    for (int j = 0; j < 4; j++) {
        int e = sp * 1024 + j * 256 + t;
        int k = e >> 7, c = e & 127;
        float s2 = 0.0f, sps = 0.0f;
        #pragma unroll
        for (int q = 0; q < 8; q++) {
            s2  += g_vpart[(((size_t)(b * 8 + q) * 64) + k) * 128 + c];
            sps += g_pspart[(b * 8 + q) * 64 + k];
        }
        float val = 2.0f * s2 - sps * anchors[k * 128 + c];
        orow[256 + e] = val;
        ss += val * val;
    }
    if (sp == 0) {
        float tv = g_t[b * 256 + t];
        orow[t] = tv;
        ss += tv * tv;
    }

    __shared__ float red[8];
    float w = warpSum(ss);
    if ((t & 31) == 0) red[t >> 5] = w;
    __syncthreads();
    if (t == 0) {
        float s = 0.0f;
        #pragma unroll
        for (int i = 0; i < 8; i++) s += red[i];
        g_ssp[b * 8 + sp] = s;
    }
}

// ----- finalK2: reduce sumsq partials + normalize ----------------------------
__global__ __launch_bounds__(1024) void finalK2(float* __restrict__ out)
{
    const int b = blockIdx.x, t = threadIdx.x;
    __shared__ float s_inv;
    if (t == 0) {
        float s = 0.0f;
        #pragma unroll
        for (int i = 0; i < 8; i++) s += g_ssp[b * 8 + i];
        s_inv = 1.0f / fmaxf(sqrtf(s), 1e-12f);
    }
    __syncthreads();
    const float inv = s_inv;
    float* orow = out + (size_t)b * 8448;
    for (int idx = t; idx < 8448; idx += 1024) orow[idx] *= inv;
}

// ---------------------------------------------------------------------------
extern "C" void kernel_launch(void* const* d_in, const int* in_sizes, int n_in,
                              void* d_out, int out_size)
{
    const float* x       = (const float*)d_in[0];
    const float* Wf      = (const float*)d_in[1];
    const float* bf      = (const float*)d_in[2];
    const float* Ws      = (const float*)d_in[3];
    const float* bs      = (const float*)d_in[4];
    const float* Wt      = (const float*)d_in[5];
    const float* bt      = (const float*)d_in[6];
    const float* anchors = (const float*)d_in[7];
    // d_in[8] = dust_bin: constant row shift, cancels in the transport plan.
    const float* sharp   = (const float*)d_in[9];
    float* out = (float*)d_out;

    static int smem_set = 0;
    if (!smem_set) {
        cudaFuncSetAttribute(gemmA_mma, cudaFuncAttributeMaxDynamicSharedMemorySize, SM_TOTAL);
        cudaFuncSetAttribute(gemmC_mma, cudaFuncAttributeMaxDynamicSharedMemorySize, SMC_TOTAL);
        cudaFuncSetAttribute(sinkhorn, cudaFuncAttributeMaxDynamicSharedMemorySize, SK_TOTAL);
        smem_set = 1;
    }

    prep<<<608, 256>>>(Wf, Ws, x, Wt, bt);
    gemmA_mma<<<dim3(8, 32), 512, SM_TOTAL>>>(x, bf, bs, sharp);
    sinkhorn<<<32, 1024, SK_TOTAL>>>();
    gemmC_mma<<<dim3(8, 32), 256, SMC_TOTAL>>>();
    finalK1<<<dim3(8, 32), 256>>>(anchors, out);
    finalK2<<<32, 1024>>>(out);
}